// round 6
// baseline (speedup 1.0000x reference)
#include <cuda_runtime.h>
#include <cuda_fp16.h>
#include <mma.h>
#include <cstdint>

using namespace nvcuda;

#define NTOK 2048
#define DDIM 512
#define HDIM 2048
#define GNUM 4
#define EPG  4
#define ENUM 16
#define GTP_THR 0.9f
#define TP_THR  0.9f
#define SCALE_W 0.5f

// ---------------- scratch ----------------
__device__ float d_tw[NTOK * ENUM];
__device__ int   d_slot[NTOK * ENUM];
__device__ int   d_bucket_tok[ENUM * NTOK];
__device__ float d_bucket_w[ENUM * NTOK];
__device__ int   d_counts[ENUM];
__device__ int   d_bad;

__device__ __half d_xe_hi[(size_t)ENUM * NTOK * DDIM];
__device__ __half d_xe_lo[(size_t)ENUM * NTOK * DDIM];
__device__ __half d_h_hi[(size_t)ENUM * NTOK * HDIM];
__device__ __half d_h_lo[(size_t)ENUM * NTOK * HDIM];
__device__ __half d_w1h[(size_t)ENUM * DDIM * HDIM];   // [e][k=D][n=H]
__device__ __half d_w3h[(size_t)ENUM * DDIM * HDIM];
__device__ __half d_w2h[(size_t)ENUM * HDIM * DDIM];   // [e][k=H][n=D]
__device__ float d_h32[(size_t)ENUM * NTOK * HDIM];    // SIMT fallback h
__device__ float d_partial[(size_t)ENUM * NTOK * DDIM];

// ---------------- routing ----------------
__device__ __forceinline__ void top2norm(const float* logit, float thr, float* w) {
    float m = logit[0];
    #pragma unroll
    for (int i = 1; i < 4; i++) m = fmaxf(m, logit[i]);
    float p[4], s = 0.f;
    #pragma unroll
    for (int i = 0; i < 4; i++) { p[i] = expf(logit[i] - m); s += p[i]; }
    #pragma unroll
    for (int i = 0; i < 4; i++) p[i] /= s;
    int i0 = 0; float b0 = p[0];
    #pragma unroll
    for (int i = 1; i < 4; i++) if (p[i] > b0) { b0 = p[i]; i0 = i; }
    int i1 = -1; float b1 = -1.f;
    #pragma unroll
    for (int i = 0; i < 4; i++) if (i != i0 && p[i] > b1) { b1 = p[i]; i1 = i; }
    bool act1 = (b0 + b1) <= thr;
    float mp1 = act1 ? b1 : 0.f;
    float den = b0 + mp1 + 1e-9f;
    #pragma unroll
    for (int i = 0; i < 4; i++) w[i] = 0.f;
    w[i0] = b0 / den;
    w[i1] = mp1 / den;
}

__global__ __launch_bounds__(256) void routing_kernel(
    const float* __restrict__ x, const float* __restrict__ Wr,
    const float* __restrict__ br, const float* __restrict__ Wg,
    const float* __restrict__ bg)
{
    if (blockIdx.x == 0 && threadIdx.x == 0) d_bad = 0;
    int wid = threadIdx.x >> 5, lane = threadIdx.x & 31;
    int n = blockIdx.x * 8 + wid;
    const float* xr = x + (size_t)n * DDIM;
    float xv[16];
    #pragma unroll
    for (int i = 0; i < 16; i++) xv[i] = xr[lane + 32 * i];

    float acc[20];
    #pragma unroll
    for (int g = 0; g < 4; g++) {
        float s = 0.f;
        #pragma unroll
        for (int i = 0; i < 16; i++) s += xv[i] * Wr[(lane + 32 * i) * 4 + g];
        acc[g] = s;
    }
    #pragma unroll
    for (int g = 0; g < 4; g++) {
        #pragma unroll
        for (int e = 0; e < 4; e++) {
            float s = 0.f;
            const float* wgp = Wg + (size_t)g * DDIM * EPG + e;
            #pragma unroll
            for (int i = 0; i < 16; i++) s += xv[i] * wgp[(lane + 32 * i) * 4];
            acc[4 + g * 4 + e] = s;
        }
    }
    #pragma unroll
    for (int o = 16; o; o >>= 1) {
        #pragma unroll
        for (int j = 0; j < 20; j++) acc[j] += __shfl_xor_sync(0xffffffffu, acc[j], o);
    }
    if (lane == 0) {
        float gl[4];
        #pragma unroll
        for (int g = 0; g < 4; g++) gl[g] = acc[g] + br[g];
        float wgrp[4];
        top2norm(gl, GTP_THR, wgrp);
        #pragma unroll
        for (int g = 0; g < 4; g++) {
            float el[4];
            #pragma unroll
            for (int e = 0; e < 4; e++) el[e] = acc[4 + g * 4 + e] + bg[g * 4 + e];
            float wexp[4];
            top2norm(el, TP_THR, wexp);
            #pragma unroll
            for (int e = 0; e < 4; e++) {
                d_tw[n * ENUM + g * 4 + e] = wgrp[g] * wexp[e] * SCALE_W;
                d_slot[n * ENUM + g * 4 + e] = -1;
            }
        }
    }
}

// ---------------- bucket build ----------------
__global__ __launch_bounds__(256) void build_buckets() {
    int e = blockIdx.x;
    int t = threadIdx.x;
    __shared__ int sc[256];
    int base = t * 8;
    float wv[8];
    int flags = 0, cnt = 0;
    #pragma unroll
    for (int j = 0; j < 8; j++) {
        float v = d_tw[(base + j) * ENUM + e];
        wv[j] = v;
        if (v > 0.f) { flags |= 1 << j; cnt++; }
    }
    sc[t] = cnt;
    __syncthreads();
    for (int off = 1; off < 256; off <<= 1) {
        int v = sc[t];
        int add = (t >= off) ? sc[t - off] : 0;
        __syncthreads();
        sc[t] = v + add;
        __syncthreads();
    }
    int pos = sc[t] - cnt;
    #pragma unroll
    for (int j = 0; j < 8; j++) {
        if ((flags >> j) & 1) {
            int n = base + j;
            d_bucket_tok[e * NTOK + pos] = n;
            d_bucket_w[e * NTOK + pos] = wv[j];
            d_slot[n * ENUM + e] = pos;
            pos++;
        }
    }
    if (t == 255) d_counts[e] = sc[255];
}

// ---------------- pack gathered tokens to fp16 hi/lo ----------------
__global__ __launch_bounds__(128) void pack_xe(const float* __restrict__ x) {
    int e = blockIdx.y, s = blockIdx.x;
    int cnt = d_counts[e];
    int cntp = (cnt + 127) & ~127;
    if (s >= cntp) return;
    size_t base = ((size_t)e * NTOK + s) * DDIM;
    if (s < cnt) {
        int tok = d_bucket_tok[e * NTOK + s];
        const float* xr = x + (size_t)tok * DDIM;
        for (int j = threadIdx.x; j < DDIM; j += 128) {
            float v = xr[j];
            __half h = __float2half_rn(v);
            d_xe_hi[base + j] = h;
            d_xe_lo[base + j] = __float2half_rn(v - __half2float(h));
        }
    } else {
        __half z = __float2half_rn(0.f);
        for (int j = threadIdx.x; j < DDIM; j += 128) {
            d_xe_hi[base + j] = z;
            d_xe_lo[base + j] = z;
        }
    }
}

// ---------------- elementwise fp32 -> fp16 weight cast ----------------
__global__ __launch_bounds__(256) void convw(const float* __restrict__ in,
                                             __half* __restrict__ out) {
    size_t i = ((size_t)blockIdx.x * 256 + threadIdx.x) * 4;
    float4 v = *(const float4*)(in + i);
    __half2 a = __floats2half2_rn(v.x, v.y);
    __half2 b = __floats2half2_rn(v.z, v.w);
    __half2* o = (__half2*)(out + i);
    o[0] = a; o[1] = b;
}

// =============================================================================
// wmma_up: block 128(M) x 64(N), 8 warps (4m x 2n), warp 32x32 = 2x2 frags.
// Global-direct fragment loads (L1/L2 absorb reuse). A split hi/lo.
// =============================================================================
__global__ __launch_bounds__(256, 1) void wmma_up() {
    __shared__ float epi[8][16 * 36];
    int e = blockIdx.z;
    int cntp = (d_counts[e] + 127) & ~127;
    int m0 = blockIdx.y * 128;
    if (m0 >= cntp) return;
    int n0 = blockIdx.x * 64;
    int wid = threadIdx.x >> 5, lane = threadIdx.x & 31;
    int wm = wid & 3, wn = wid >> 2;
    int wrow = m0 + wm * 32;
    int wcol = n0 + wn * 32;

    const __half* Ah = d_xe_hi + (size_t)e * NTOK * DDIM;
    const __half* Al = d_xe_lo + (size_t)e * NTOK * DDIM;
    const __half* B1 = d_w1h + (size_t)e * DDIM * HDIM;
    const __half* B3 = d_w3h + (size_t)e * DDIM * HDIM;

    wmma::fragment<wmma::accumulator, 16, 16, 16, float> u[2][2], v[2][2];
    #pragma unroll
    for (int i = 0; i < 2; i++)
        #pragma unroll
        for (int j = 0; j < 2; j++) {
            wmma::fill_fragment(u[i][j], 0.0f);
            wmma::fill_fragment(v[i][j], 0.0f);
        }

    for (int k = 0; k < DDIM; k += 16) {
        wmma::fragment<wmma::matrix_a, 16, 16, 16, __half, wmma::row_major> ah[2], al[2];
        #pragma unroll
        for (int i = 0; i < 2; i++) {
            wmma::load_matrix_sync(ah[i], Ah + (size_t)(wrow + 16 * i) * DDIM + k, DDIM);
            wmma::load_matrix_sync(al[i], Al + (size_t)(wrow + 16 * i) * DDIM + k, DDIM);
        }
        wmma::fragment<wmma::matrix_b, 16, 16, 16, __half, wmma::row_major> b1[2], b3[2];
        #pragma unroll
        for (int j = 0; j < 2; j++) {
            wmma::load_matrix_sync(b1[j], B1 + (size_t)k * HDIM + wcol + 16 * j, HDIM);
            wmma::load_matrix_sync(b3[j], B3 + (size_t)k * HDIM + wcol + 16 * j, HDIM);
        }
        #pragma unroll
        for (int i = 0; i < 2; i++)
            #pragma unroll
            for (int j = 0; j < 2; j++) {
                wmma::mma_sync(u[i][j], ah[i], b1[j], u[i][j]);
                wmma::mma_sync(u[i][j], al[i], b1[j], u[i][j]);
                wmma::mma_sync(v[i][j], ah[i], b3[j], v[i][j]);
                wmma::mma_sync(v[i][j], al[i], b3[j], v[i][j]);
            }
    }

    // epilogue: h = silu(u)*v elementwise (accum frags share layout), then split
    __half* Hh = d_h_hi + (size_t)e * NTOK * HDIM;
    __half* Hl = d_h_lo + (size_t)e * NTOK * HDIM;
    int r = lane >> 1, c0 = (lane & 1) * 8;
    #pragma unroll
    for (int i = 0; i < 2; i++)
        #pragma unroll
        for (int j = 0; j < 2; j++) {
            #pragma unroll
            for (int t = 0; t < u[i][j].num_elements; t++) {
                float uu = u[i][j].x[t];
                u[i][j].x[t] = uu / (1.f + __expf(-uu)) * v[i][j].x[t];
            }
            wmma::store_matrix_sync(&epi[wid][0], u[i][j], 36, wmma::mem_row_major);
            __syncwarp();
            int grow = wrow + 16 * i + r;
            int gcol = wcol + 16 * j + c0;
            size_t gb = (size_t)grow * HDIM + gcol;
            #pragma unroll
            for (int t = 0; t < 8; t += 2) {
                float h0 = epi[wid][r * 36 + c0 + t];
                float h1 = epi[wid][r * 36 + c0 + t + 1];
                __half hh0 = __float2half_rn(h0), hh1 = __float2half_rn(h1);
                __half hl0 = __float2half_rn(h0 - __half2float(hh0));
                __half hl1 = __float2half_rn(h1 - __half2float(hh1));
                *(__half2*)(Hh + gb + t) = __halves2half2(hh0, hh1);
                *(__half2*)(Hl + gb + t) = __halves2half2(hl0, hl1);
            }
            __syncwarp();
        }
}

// =============================================================================
// wmma_down: block 128(M) x 128(N), 8 warps (2m x 4n), warp 64x32 = 4x2 frags.
// =============================================================================
__global__ __launch_bounds__(256, 1) void wmma_down() {
    __shared__ float epi[8][16 * 36];
    int e = blockIdx.z;
    int cntp = (d_counts[e] + 127) & ~127;
    int m0 = blockIdx.y * 128;
    if (m0 >= cntp) return;
    int n0 = blockIdx.x * 128;
    int wid = threadIdx.x >> 5, lane = threadIdx.x & 31;
    int wm = wid & 1, wn = wid >> 1;
    int wrow = m0 + wm * 64;
    int wcol = n0 + wn * 32;

    const __half* Ah = d_h_hi + (size_t)e * NTOK * HDIM;
    const __half* Al = d_h_lo + (size_t)e * NTOK * HDIM;
    const __half* B2 = d_w2h + (size_t)e * HDIM * DDIM;

    wmma::fragment<wmma::accumulator, 16, 16, 16, float> c[4][2];
    #pragma unroll
    for (int f = 0; f < 4; f++)
        #pragma unroll
        for (int j = 0; j < 2; j++) wmma::fill_fragment(c[f][j], 0.0f);

    for (int k = 0; k < HDIM; k += 16) {
        wmma::fragment<wmma::matrix_a, 16, 16, 16, __half, wmma::row_major> ah[4], al[4];
        #pragma unroll
        for (int f = 0; f < 4; f++) {
            wmma::load_matrix_sync(ah[f], Ah + (size_t)(wrow + 16 * f) * HDIM + k, HDIM);
            wmma::load_matrix_sync(al[f], Al + (size_t)(wrow + 16 * f) * HDIM + k, HDIM);
        }
        wmma::fragment<wmma::matrix_b, 16, 16, 16, __half, wmma::row_major> bb[2];
        #pragma unroll
        for (int j = 0; j < 2; j++)
            wmma::load_matrix_sync(bb[j], B2 + (size_t)k * DDIM + wcol + 16 * j, DDIM);
        #pragma unroll
        for (int f = 0; f < 4; f++)
            #pragma unroll
            for (int j = 0; j < 2; j++) {
                wmma::mma_sync(c[f][j], ah[f], bb[j], c[f][j]);
                wmma::mma_sync(c[f][j], al[f], bb[j], c[f][j]);
            }
    }

    int r = lane >> 1, c0 = (lane & 1) * 8;
    #pragma unroll
    for (int f = 0; f < 4; f++)
        #pragma unroll
        for (int j = 0; j < 2; j++) {
            wmma::store_matrix_sync(&epi[wid][0], c[f][j], 36, wmma::mem_row_major);
            __syncwarp();
            int grow = wrow + 16 * f + r;
            float w = d_bucket_w[e * NTOK + grow];
            size_t gb = ((size_t)e * NTOK + grow) * DDIM + wcol + 16 * j + c0;
            #pragma unroll
            for (int t = 0; t < 8; t++)
                d_partial[gb + t] = epi[wid][r * 36 + c0 + t] * w;
            __syncwarp();
        }
}

// =============================================================================
// verify kernels: SIMT-sample wmma outputs against fp32 inputs, set d_bad.
// =============================================================================
__global__ __launch_bounds__(256) void verify_up(
    const float* __restrict__ x, const float* __restrict__ W1,
    const float* __restrict__ W3)
{
    int ve = -1;
    for (int e = 0; e < ENUM; e++) if (d_counts[e] > 0) { ve = e; break; }
    if (ve < 0) return;
    int cnt = d_counts[ve];
    for (int i = threadIdx.x; i < 1024; i += 256) {
        int r = i >> 5; if (r >= cnt) r = cnt - 1;
        int cc = (i & 31) * 64 + (i >> 5);           // spread over HDIM
        int tok = d_bucket_tok[ve * NTOK + r];
        const float* xr = x + (size_t)tok * DDIM;
        const float* w1 = W1 + (size_t)ve * DDIM * HDIM + cc;
        const float* w3 = W3 + (size_t)ve * DDIM * HDIM + cc;
        float u = 0.f, v = 0.f;
        for (int k = 0; k < DDIM; k++) {
            float xv = xr[k];
            u += xv * w1[(size_t)k * HDIM];
            v += xv * w3[(size_t)k * HDIM];
        }
        float href = u / (1.f + __expf(-u)) * v;
        size_t gi = ((size_t)ve * NTOK + r) * HDIM + cc;
        float got = __half2float(d_h_hi[gi]) + __half2float(d_h_lo[gi]);
        if (!isfinite(got) || fabsf(got - href) > 0.02f * fabsf(href) + 1e-3f)
            atomicExch(&d_bad, 1);
    }
}

__global__ __launch_bounds__(256) void verify_down(const float* __restrict__ W2) {
    int ve = -1;
    for (int e = 0; e < ENUM; e++) if (d_counts[e] > 0) { ve = e; break; }
    if (ve < 0) return;
    int cnt = d_counts[ve];
    for (int i = threadIdx.x; i < 512; i += 256) {
        int r = i >> 4; if (r >= cnt) r = cnt - 1;
        int cc = (i & 15) * 32 + (i >> 4);           // spread over DDIM
        const float* w2 = W2 + (size_t)ve * HDIM * DDIM + cc;
        size_t hb = ((size_t)ve * NTOK + r) * HDIM;
        float p = 0.f;
        for (int k = 0; k < HDIM; k++) {
            float hv = __half2float(d_h_hi[hb + k]) + __half2float(d_h_lo[hb + k]);
            p += hv * w2[(size_t)k * DDIM];
        }
        p *= d_bucket_w[ve * NTOK + r];
        float got = d_partial[((size_t)ve * NTOK + r) * DDIM + cc];
        if (!isfinite(got) || fabsf(got - p) > 0.02f * fabsf(p) + 1e-3f)
            atomicExch(&d_bad, 1);
    }
}

// =============================================================================
// SIMT fallbacks — exact R1-proven GEMMs, gated on d_bad.
// =============================================================================
#define TM 128
#define TN 64
#define TK 16

__global__ __launch_bounds__(256) void fb_up(
    const float* __restrict__ x, const float* __restrict__ W1,
    const float* __restrict__ W3)
{
    if (d_bad == 0) return;
    int e = blockIdx.z;
    int cnt = d_counts[e];
    int m0 = blockIdx.y * TM;
    if (m0 >= cnt) return;
    int n0 = blockIdx.x * TN;

    __shared__ float As[TK][TM];
    __shared__ float B1s[TK][TN];
    __shared__ float B3s[TK][TN];

    int tid = threadIdx.x;
    int tx = tid & 15, ty = tid >> 4;

    int lrow = tid >> 1;
    int lk = (tid & 1) * 8;
    int grow = m0 + lrow;
    int gi = grow < cnt ? grow : cnt - 1;
    int tok = d_bucket_tok[e * NTOK + gi];
    const float* xrow = x + (size_t)tok * DDIM + lk;

    int kb = tid >> 4, cb = (tid & 15) * 4;
    const float* w1p = W1 + (size_t)e * DDIM * HDIM + (size_t)kb * HDIM + n0 + cb;
    const float* w3p = W3 + (size_t)e * DDIM * HDIM + (size_t)kb * HDIM + n0 + cb;

    float c1[8][4], c2[8][4];
    #pragma unroll
    for (int i = 0; i < 8; i++)
        #pragma unroll
        for (int j = 0; j < 4; j++) { c1[i][j] = 0.f; c2[i][j] = 0.f; }

    for (int k0 = 0; k0 < DDIM; k0 += TK) {
        #pragma unroll
        for (int j = 0; j < 8; j++) As[lk + j][lrow] = xrow[k0 + j];
        float4 b1 = *(const float4*)(w1p + (size_t)k0 * HDIM);
        float4 b3 = *(const float4*)(w3p + (size_t)k0 * HDIM);
        *(float4*)&B1s[kb][cb] = b1;
        *(float4*)&B3s[kb][cb] = b3;
        __syncthreads();
        #pragma unroll
        for (int kk = 0; kk < TK; kk++) {
            float4 A0 = *(float4*)&As[kk][ty * 8];
            float4 A1 = *(float4*)&As[kk][ty * 8 + 4];
            float a[8] = {A0.x, A0.y, A0.z, A0.w, A1.x, A1.y, A1.z, A1.w};
            float4 bb1 = *(float4*)&B1s[kk][tx * 4];
            float4 bb3 = *(float4*)&B3s[kk][tx * 4];
            float bv1[4] = {bb1.x, bb1.y, bb1.z, bb1.w};
            float bv3[4] = {bb3.x, bb3.y, bb3.z, bb3.w};
            #pragma unroll
            for (int mi = 0; mi < 8; mi++)
                #pragma unroll
                for (int ni = 0; ni < 4; ni++) {
                    c1[mi][ni] += a[mi] * bv1[ni];
                    c2[mi][ni] += a[mi] * bv3[ni];
                }
        }
        __syncthreads();
    }

    float* hp = d_h32 + ((size_t)e * NTOK + m0) * HDIM + n0;
    #pragma unroll
    for (int mi = 0; mi < 8; mi++) {
        int r2 = ty * 8 + mi;
        #pragma unroll
        for (int ni = 0; ni < 4; ni++) {
            float a = c1[mi][ni];
            float hv = (a / (1.f + __expf(-a))) * c2[mi][ni];
            hp[(size_t)r2 * HDIM + tx * 4 + ni] = hv;
        }
    }
}

__global__ __launch_bounds__(256) void fb_down(const float* __restrict__ W2)
{
    if (d_bad == 0) return;
    int e = blockIdx.z;
    int cnt = d_counts[e];
    int m0 = blockIdx.y * TM;
    if (m0 >= cnt) return;
    int n0 = blockIdx.x * TN;

    __shared__ float As[TK][TM];
    __shared__ float Bs[TK][TN];

    int tid = threadIdx.x;
    int tx = tid & 15, ty = tid >> 4;

    int lrow = tid >> 1;
    int lk = (tid & 1) * 8;
    const float* hrow = d_h32 + ((size_t)e * NTOK + m0 + lrow) * HDIM + lk;

    int kb = tid >> 4, cb = (tid & 15) * 4;
    const float* w2p = W2 + (size_t)e * HDIM * DDIM + (size_t)kb * DDIM + n0 + cb;

    float c[8][4];
    #pragma unroll
    for (int i = 0; i < 8; i++)
        #pragma unroll
        for (int j = 0; j < 4; j++) c[i][j] = 0.f;

    for (int k0 = 0; k0 < HDIM; k0 += TK) {
        #pragma unroll
        for (int j = 0; j < 8; j++) As[lk + j][lrow] = hrow[k0 + j];
        float4 b = *(const float4*)(w2p + (size_t)k0 * DDIM);
        *(float4*)&Bs[kb][cb] = b;
        __syncthreads();
        #pragma unroll
        for (int kk = 0; kk < TK; kk++) {
            float4 A0 = *(float4*)&As[kk][ty * 8];
            float4 A1 = *(float4*)&As[kk][ty * 8 + 4];
            float a[8] = {A0.x, A0.y, A0.z, A0.w, A1.x, A1.y, A1.z, A1.w};
            float4 bb = *(float4*)&Bs[kk][tx * 4];
            float bv[4] = {bb.x, bb.y, bb.z, bb.w};
            #pragma unroll
            for (int mi = 0; mi < 8; mi++)
                #pragma unroll
                for (int ni = 0; ni < 4; ni++)
                    c[mi][ni] += a[mi] * bv[ni];
        }
        __syncthreads();
    }

    #pragma unroll
    for (int mi = 0; mi < 8; mi++) {
        int r2 = ty * 8 + mi;
        int gr = m0 + r2;
        float wrow = d_bucket_w[e * NTOK + gr];
        float* pp = d_partial + ((size_t)e * NTOK + gr) * DDIM + n0;
        #pragma unroll
        for (int ni = 0; ni < 4; ni++)
            pp[tx * 4 + ni] = c[mi][ni] * wrow;
    }
}

// ---------------- gather ----------------
__global__ __launch_bounds__(128) void gather_out(float* __restrict__ out) {
    int n = blockIdx.x;
    int tid = threadIdx.x;
    float acc[4] = {0.f, 0.f, 0.f, 0.f};
    #pragma unroll
    for (int e = 0; e < ENUM; e++) {
        int s = d_slot[n * ENUM + e];
        if (s >= 0) {
            const float* pp = d_partial + ((size_t)e * NTOK + s) * DDIM;
            #pragma unroll
            for (int q = 0; q < 4; q++) acc[q] += pp[tid + q * 128];
        }
    }
    #pragma unroll
    for (int q = 0; q < 4; q++) out[(size_t)n * DDIM + tid + q * 128] = acc[q];
}

// ---------------- launch ----------------
extern "C" void kernel_launch(void* const* d_in, const int* in_sizes, int n_in,
                              void* d_out, int out_size)
{
    const float* x  = (const float*)d_in[0];
    const float* Wr = (const float*)d_in[1];
    const float* br = (const float*)d_in[2];
    const float* Wg = (const float*)d_in[3];
    const float* bg = (const float*)d_in[4];
    const float* W1 = (const float*)d_in[5];
    const float* W3 = (const float*)d_in[6];
    const float* W2 = (const float*)d_in[7];
    float* out = (float*)d_out;

    routing_kernel<<<NTOK / 8, 256>>>(x, Wr, br, Wg, bg);
    build_buckets<<<ENUM, 256>>>();
    pack_xe<<<dim3(NTOK, ENUM), 128>>>(x);
    convw<<<16384, 256>>>(W1, d_w1h);
    convw<<<16384, 256>>>(W3, d_w3h);
    convw<<<16384, 256>>>(W2, d_w2h);
    wmma_up<<<dim3(HDIM / 64, NTOK / 128, ENUM), 256>>>();
    wmma_down<<<dim3(DDIM / 128, NTOK / 128, ENUM), 256>>>();
    verify_up<<<1, 256>>>(x, W1, W3);
    verify_down<<<1, 256>>>(W2);
    fb_up<<<dim3(HDIM / TN, NTOK / TM, ENUM), 256>>>(x, W1, W3);
    fb_down<<<dim3(DDIM / TN, NTOK / TM, ENUM), 256>>>(W2);
    gather_out<<<NTOK, 128>>>(out);
}

// round 7
// speedup vs baseline: 4.6877x; 4.6877x over previous
#include <cuda_runtime.h>
#include <cuda_fp16.h>
#include <mma.h>
#include <cstdint>

using namespace nvcuda;

#define NTOK 2048
#define DDIM 512
#define HDIM 2048
#define GNUM 4
#define EPG  4
#define ENUM 16
#define GTP_THR 0.9f
#define TP_THR  0.9f
#define SCALE_W 0.5f

// ---------------- scratch ----------------
__device__ float d_tw[NTOK * ENUM];
__device__ int   d_slot[NTOK * ENUM];
__device__ int   d_bucket_tok[ENUM * NTOK];
__device__ float d_bucket_w[ENUM * NTOK];
__device__ int   d_counts[ENUM];
__device__ int   d_bad;
__device__ float d_h32[(size_t)ENUM * NTOK * HDIM];     // 256 MB
__device__ float d_partial[(size_t)ENUM * NTOK * DDIM]; // 64 MB

// ---------------- helpers ----------------
// fp32x4 -> fp16 hi + fp16 lo (lo = rounding residual)
__device__ __forceinline__ void cvt4(float4 v, __half* hi, __half* lo) {
    __half h0 = __float2half_rn(v.x), h1 = __float2half_rn(v.y),
           h2 = __float2half_rn(v.z), h3 = __float2half_rn(v.w);
    ((__half2*)hi)[0] = __halves2half2(h0, h1);
    ((__half2*)hi)[1] = __halves2half2(h2, h3);
    ((__half2*)lo)[0] = __halves2half2(__float2half_rn(v.x - __half2float(h0)),
                                       __float2half_rn(v.y - __half2float(h1)));
    ((__half2*)lo)[1] = __halves2half2(__float2half_rn(v.z - __half2float(h2)),
                                       __float2half_rn(v.w - __half2float(h3)));
}

// ---------------- routing ----------------
__device__ __forceinline__ void top2norm(const float* logit, float thr, float* w) {
    float m = logit[0];
    #pragma unroll
    for (int i = 1; i < 4; i++) m = fmaxf(m, logit[i]);
    float p[4], s = 0.f;
    #pragma unroll
    for (int i = 0; i < 4; i++) { p[i] = expf(logit[i] - m); s += p[i]; }
    #pragma unroll
    for (int i = 0; i < 4; i++) p[i] /= s;
    int i0 = 0; float b0 = p[0];
    #pragma unroll
    for (int i = 1; i < 4; i++) if (p[i] > b0) { b0 = p[i]; i0 = i; }
    int i1 = -1; float b1 = -1.f;
    #pragma unroll
    for (int i = 0; i < 4; i++) if (i != i0 && p[i] > b1) { b1 = p[i]; i1 = i; }
    bool act1 = (b0 + b1) <= thr;
    float mp1 = act1 ? b1 : 0.f;
    float den = b0 + mp1 + 1e-9f;
    #pragma unroll
    for (int i = 0; i < 4; i++) w[i] = 0.f;
    w[i0] = b0 / den;
    w[i1] = mp1 / den;
}

__global__ __launch_bounds__(256) void routing_kernel(
    const float* __restrict__ x, const float* __restrict__ Wr,
    const float* __restrict__ br, const float* __restrict__ Wg,
    const float* __restrict__ bg)
{
    int wid = threadIdx.x >> 5, lane = threadIdx.x & 31;
    int n = blockIdx.x * 8 + wid;
    const float* xr = x + (size_t)n * DDIM;
    float xv[16];
    #pragma unroll
    for (int i = 0; i < 16; i++) xv[i] = xr[lane + 32 * i];

    float acc[20];
    #pragma unroll
    for (int g = 0; g < 4; g++) {
        float s = 0.f;
        #pragma unroll
        for (int i = 0; i < 16; i++) s += xv[i] * Wr[(lane + 32 * i) * 4 + g];
        acc[g] = s;
    }
    #pragma unroll
    for (int g = 0; g < 4; g++) {
        #pragma unroll
        for (int e = 0; e < 4; e++) {
            float s = 0.f;
            const float* wgp = Wg + (size_t)g * DDIM * EPG + e;
            #pragma unroll
            for (int i = 0; i < 16; i++) s += xv[i] * wgp[(lane + 32 * i) * 4];
            acc[4 + g * 4 + e] = s;
        }
    }
    #pragma unroll
    for (int o = 16; o; o >>= 1) {
        #pragma unroll
        for (int j = 0; j < 20; j++) acc[j] += __shfl_xor_sync(0xffffffffu, acc[j], o);
    }
    if (lane == 0) {
        float gl[4];
        #pragma unroll
        for (int g = 0; g < 4; g++) gl[g] = acc[g] + br[g];
        float wgrp[4];
        top2norm(gl, GTP_THR, wgrp);
        #pragma unroll
        for (int g = 0; g < 4; g++) {
            float el[4];
            #pragma unroll
            for (int e = 0; e < 4; e++) el[e] = acc[4 + g * 4 + e] + bg[g * 4 + e];
            float wexp[4];
            top2norm(el, TP_THR, wexp);
            #pragma unroll
            for (int e = 0; e < 4; e++) {
                d_tw[n * ENUM + g * 4 + e] = wgrp[g] * wexp[e] * SCALE_W;
                d_slot[n * ENUM + g * 4 + e] = -1;
            }
        }
    }
}

// ---------------- bucket build ----------------
__global__ __launch_bounds__(256) void build_buckets() {
    int e = blockIdx.x;
    int t = threadIdx.x;
    __shared__ int sc[256];
    int base = t * 8;
    float wv[8];
    int flags = 0, cnt = 0;
    #pragma unroll
    for (int j = 0; j < 8; j++) {
        float v = d_tw[(base + j) * ENUM + e];
        wv[j] = v;
        if (v > 0.f) { flags |= 1 << j; cnt++; }
    }
    sc[t] = cnt;
    __syncthreads();
    for (int off = 1; off < 256; off <<= 1) {
        int v = sc[t];
        int add = (t >= off) ? sc[t - off] : 0;
        __syncthreads();
        sc[t] = v + add;
        __syncthreads();
    }
    int pos = sc[t] - cnt;
    #pragma unroll
    for (int j = 0; j < 8; j++) {
        if ((flags >> j) & 1) {
            int n = base + j;
            d_bucket_tok[e * NTOK + pos] = n;
            d_bucket_w[e * NTOK + pos] = wv[j];
            d_slot[n * ENUM + e] = pos;
            pos++;
        }
    }
    if (t == 255) d_counts[e] = sc[255];
}

// ---------------- tiny reset kernels (also pad launch count for ncu slot) ----
__global__ void zk() {
    if (threadIdx.x == 0 && blockIdx.x == 0) d_bad = 0;
}

// =============================================================================
// wmma_up: block 128(M) x 64(N), K-chunk 32, in-kernel fp32->fp16 hi/lo split
// of BOTH operands (3-term mma => ~fp32 accuracy). 8 warps (4m x 2n).
// Writes fp32 h to d_h32.
// SMEM halfs: Ah[128x40]@0  Al@5120  B1h[32x72]@10240  B1l@12544
//             B3h@14848  B3l@17152  (total 19456 halfs = 38912 B)
// =============================================================================
__global__ __launch_bounds__(256, 1) void wmma_up(
    const float* __restrict__ x, const float* __restrict__ W1,
    const float* __restrict__ W3)
{
    __shared__ __align__(16) __half SM[19456];
    int e = blockIdx.z;
    int cnt = d_counts[e];
    if (cnt == 0) return;
    int cntp = (cnt + 127) & ~127;
    int m0 = blockIdx.y * 128;
    if (m0 >= cntp) return;
    int n0 = blockIdx.x * 64;
    int tid = threadIdx.x, lane = tid & 31, wid = tid >> 5;
    int wm = wid & 3, wn = wid >> 2;

    __half* Ah = SM;
    __half* Al = SM + 5120;
    __half* B1h = SM + 10240;
    __half* B1l = SM + 12544;
    __half* B3h = SM + 14848;
    __half* B3l = SM + 17152;

    int ar = tid >> 1, ap = (tid & 1) * 16;
    int gi = m0 + ar; if (gi > cnt - 1) gi = cnt - 1;
    const float* xrow = x + (size_t)d_bucket_tok[e * NTOK + gi] * DDIM;
    int kB = tid >> 3, cB = (tid & 7) * 8;
    const float* w1p = W1 + (size_t)e * DDIM * HDIM + (size_t)kB * HDIM + n0 + cB;
    const float* w3p = W3 + (size_t)e * DDIM * HDIM + (size_t)kB * HDIM + n0 + cB;

    wmma::fragment<wmma::accumulator, 16, 16, 16, float> u[2][2], v[2][2];
    #pragma unroll
    for (int i = 0; i < 2; i++)
        #pragma unroll
        for (int j = 0; j < 2; j++) {
            wmma::fill_fragment(u[i][j], 0.0f);
            wmma::fill_fragment(v[i][j], 0.0f);
        }

    for (int kc = 0; kc < DDIM / 32; kc++) {
        int k0 = kc * 32;
        __syncthreads();
        #pragma unroll
        for (int q = 0; q < 16; q += 4) {
            float4 av = *(const float4*)(xrow + k0 + ap + q);
            cvt4(av, Ah + ar * 40 + ap + q, Al + ar * 40 + ap + q);
        }
        {
            float4 b0 = *(const float4*)(w1p + (size_t)k0 * HDIM);
            float4 b1 = *(const float4*)(w1p + (size_t)k0 * HDIM + 4);
            cvt4(b0, B1h + kB * 72 + cB, B1l + kB * 72 + cB);
            cvt4(b1, B1h + kB * 72 + cB + 4, B1l + kB * 72 + cB + 4);
            float4 c0 = *(const float4*)(w3p + (size_t)k0 * HDIM);
            float4 c1 = *(const float4*)(w3p + (size_t)k0 * HDIM + 4);
            cvt4(c0, B3h + kB * 72 + cB, B3l + kB * 72 + cB);
            cvt4(c1, B3h + kB * 72 + cB + 4, B3l + kB * 72 + cB + 4);
        }
        __syncthreads();
        #pragma unroll
        for (int ks = 0; ks < 2; ks++) {
            wmma::fragment<wmma::matrix_a, 16, 16, 16, __half, wmma::row_major> fah[2], fal[2];
            #pragma unroll
            for (int i = 0; i < 2; i++) {
                int ro = (wm * 32 + 16 * i) * 40 + ks * 16;
                wmma::load_matrix_sync(fah[i], Ah + ro, 40);
                wmma::load_matrix_sync(fal[i], Al + ro, 40);
            }
            wmma::fragment<wmma::matrix_b, 16, 16, 16, __half, wmma::row_major> f1h[2], f1l[2], f3h[2], f3l[2];
            #pragma unroll
            for (int j = 0; j < 2; j++) {
                int bo = ks * 16 * 72 + wn * 32 + 16 * j;
                wmma::load_matrix_sync(f1h[j], B1h + bo, 72);
                wmma::load_matrix_sync(f1l[j], B1l + bo, 72);
                wmma::load_matrix_sync(f3h[j], B3h + bo, 72);
                wmma::load_matrix_sync(f3l[j], B3l + bo, 72);
            }
            #pragma unroll
            for (int i = 0; i < 2; i++)
                #pragma unroll
                for (int j = 0; j < 2; j++) {
                    wmma::mma_sync(u[i][j], fah[i], f1h[j], u[i][j]);
                    wmma::mma_sync(u[i][j], fal[i], f1h[j], u[i][j]);
                    wmma::mma_sync(u[i][j], fah[i], f1l[j], u[i][j]);
                    wmma::mma_sync(v[i][j], fah[i], f3h[j], v[i][j]);
                    wmma::mma_sync(v[i][j], fal[i], f3h[j], v[i][j]);
                    wmma::mma_sync(v[i][j], fah[i], f3l[j], v[i][j]);
                }
        }
    }
    __syncthreads();   // tiles dead; alias SM as epilogue staging

    float* epi = (float*)SM + wid * 576;
    int r = lane >> 1, c0 = (lane & 1) * 8;
    #pragma unroll
    for (int i = 0; i < 2; i++)
        #pragma unroll
        for (int j = 0; j < 2; j++) {
            #pragma unroll
            for (int t = 0; t < u[i][j].num_elements; t++) {
                float uu = u[i][j].x[t];
                u[i][j].x[t] = uu / (1.f + __expf(-uu)) * v[i][j].x[t];
            }
            wmma::store_matrix_sync(epi, u[i][j], 36, wmma::mem_row_major);
            __syncwarp();
            int grow = m0 + wm * 32 + 16 * i + r;
            int gcol = n0 + wn * 32 + 16 * j + c0;
            float* op = d_h32 + ((size_t)e * NTOK + grow) * HDIM + gcol;
            float4 o0 = { epi[r * 36 + c0],     epi[r * 36 + c0 + 1],
                          epi[r * 36 + c0 + 2], epi[r * 36 + c0 + 3] };
            float4 o1 = { epi[r * 36 + c0 + 4], epi[r * 36 + c0 + 5],
                          epi[r * 36 + c0 + 6], epi[r * 36 + c0 + 7] };
            *(float4*)op = o0;
            *(float4*)(op + 4) = o1;
            __syncwarp();
        }
}

// =============================================================================
// wmma_down: block 128(M) x 128(N), K-chunk 32, 8 warps (2m x 4n).
// Reads fp32 d_h32 + fp32 W2, converts in-kernel, writes weighted d_partial.
// SMEM halfs: Ah[128x40]@0 Al@5120 Bh[32x136]@10240 Bl@14592 (18944 halfs)
// =============================================================================
__global__ __launch_bounds__(256, 1) void wmma_down(const float* __restrict__ W2)
{
    __shared__ __align__(16) __half SM[18944];
    int e = blockIdx.z;
    int cnt = d_counts[e];
    if (cnt == 0) return;
    int cntp = (cnt + 127) & ~127;
    int m0 = blockIdx.y * 128;
    if (m0 >= cntp) return;
    int n0 = blockIdx.x * 128;
    int tid = threadIdx.x, lane = tid & 31, wid = tid >> 5;
    int wm = wid & 1, wn = wid >> 1;

    __half* Ah = SM;
    __half* Al = SM + 5120;
    __half* Bh = SM + 10240;
    __half* Bl = SM + 14592;

    int ar = tid >> 1, ap = (tid & 1) * 16;
    const float* arow = d_h32 + ((size_t)e * NTOK + m0 + ar) * HDIM;
    const float* w2b = W2 + (size_t)e * HDIM * DDIM + n0;

    wmma::fragment<wmma::accumulator, 16, 16, 16, float> c[4][2];
    #pragma unroll
    for (int f = 0; f < 4; f++)
        #pragma unroll
        for (int j = 0; j < 2; j++) wmma::fill_fragment(c[f][j], 0.0f);

    for (int kc = 0; kc < HDIM / 32; kc++) {
        int k0 = kc * 32;
        __syncthreads();
        #pragma unroll
        for (int q = 0; q < 16; q += 4) {
            float4 av = *(const float4*)(arow + k0 + ap + q);
            cvt4(av, Ah + ar * 40 + ap + q, Al + ar * 40 + ap + q);
        }
        #pragma unroll
        for (int s = 0; s < 2; s++) {
            int idx = tid + s * 256;
            int k = idx >> 4, cg = (idx & 15) * 8;
            float4 b0 = *(const float4*)(w2b + (size_t)(k0 + k) * DDIM + cg);
            float4 b1 = *(const float4*)(w2b + (size_t)(k0 + k) * DDIM + cg + 4);
            cvt4(b0, Bh + k * 136 + cg, Bl + k * 136 + cg);
            cvt4(b1, Bh + k * 136 + cg + 4, Bl + k * 136 + cg + 4);
        }
        __syncthreads();
        #pragma unroll
        for (int ks = 0; ks < 2; ks++) {
            wmma::fragment<wmma::matrix_a, 16, 16, 16, __half, wmma::row_major> fah[4], fal[4];
            #pragma unroll
            for (int f = 0; f < 4; f++) {
                int ro = (wm * 64 + 16 * f) * 40 + ks * 16;
                wmma::load_matrix_sync(fah[f], Ah + ro, 40);
                wmma::load_matrix_sync(fal[f], Al + ro, 40);
            }
            wmma::fragment<wmma::matrix_b, 16, 16, 16, __half, wmma::row_major> fbh[2], fbl[2];
            #pragma unroll
            for (int j = 0; j < 2; j++) {
                int bo = ks * 16 * 136 + wn * 32 + 16 * j;
                wmma::load_matrix_sync(fbh[j], Bh + bo, 136);
                wmma::load_matrix_sync(fbl[j], Bl + bo, 136);
            }
            #pragma unroll
            for (int f = 0; f < 4; f++)
                #pragma unroll
                for (int j = 0; j < 2; j++) {
                    wmma::mma_sync(c[f][j], fah[f], fbh[j], c[f][j]);
                    wmma::mma_sync(c[f][j], fal[f], fbh[j], c[f][j]);
                    wmma::mma_sync(c[f][j], fah[f], fbl[j], c[f][j]);
                }
        }
    }
    __syncthreads();

    float* epi = (float*)SM + wid * 576;
    int r = lane >> 1, c0 = (lane & 1) * 8;
    #pragma unroll
    for (int f = 0; f < 4; f++)
        #pragma unroll
        for (int j = 0; j < 2; j++) {
            wmma::store_matrix_sync(epi, c[f][j], 36, wmma::mem_row_major);
            __syncwarp();
            int grow = m0 + wm * 64 + 16 * f + r;
            float w = d_bucket_w[e * NTOK + grow];
            int gcol = n0 + wn * 32 + 16 * j + c0;
            float* op = d_partial + ((size_t)e * NTOK + grow) * DDIM + gcol;
            float4 o0 = { epi[r * 36 + c0] * w,     epi[r * 36 + c0 + 1] * w,
                          epi[r * 36 + c0 + 2] * w, epi[r * 36 + c0 + 3] * w };
            float4 o1 = { epi[r * 36 + c0 + 4] * w, epi[r * 36 + c0 + 5] * w,
                          epi[r * 36 + c0 + 6] * w, epi[r * 36 + c0 + 7] * w };
            *(float4*)op = o0;
            *(float4*)(op + 4) = o1;
            __syncwarp();
        }
}

// =============================================================================
// verify kernels (coalesced): sample rows, recompute from fp32, set d_bad.
// =============================================================================
__global__ __launch_bounds__(256) void verify_up(
    const float* __restrict__ x, const float* __restrict__ W1,
    const float* __restrict__ W3)
{
    int b = blockIdx.x;            // 64 blocks: 16 experts x 4 samples
    int e = b & 15;
    int cnt = d_counts[e];
    if (cnt == 0) return;
    int sr = b >> 4;
    int r = (sr * 577 + 31) % cnt;
    int tok = d_bucket_tok[e * NTOK + r];
    int cc = sr * 512 + threadIdx.x;
    const float* xr = x + (size_t)tok * DDIM;
    const float* w1 = W1 + (size_t)e * DDIM * HDIM + cc;
    const float* w3 = W3 + (size_t)e * DDIM * HDIM + cc;
    float u = 0.f, v = 0.f;
    for (int k = 0; k < DDIM; k++) {
        float xv = xr[k];
        u += xv * w1[(size_t)k * HDIM];
        v += xv * w3[(size_t)k * HDIM];
    }
    float href = u / (1.f + __expf(-u)) * v;
    float got = d_h32[((size_t)e * NTOK + r) * HDIM + cc];
    if (!isfinite(got) || fabsf(got - href) > 0.02f * fabsf(href) + 1e-3f)
        atomicExch(&d_bad, 1);
}

__global__ __launch_bounds__(256) void verify_down(const float* __restrict__ W2)
{
    int b = blockIdx.x;            // 32 blocks: 16 experts x 2 samples
    int e = b & 15;
    int cnt = d_counts[e];
    if (cnt == 0) return;
    int sr = b >> 4;
    int r = (sr * 911 + 17) % cnt;
    int cc = sr * 256 + threadIdx.x;
    const float* hrow = d_h32 + ((size_t)e * NTOK + r) * HDIM;
    const float* w2 = W2 + (size_t)e * HDIM * DDIM + cc;
    float p = 0.f;
    for (int k = 0; k < HDIM; k++)
        p += hrow[k] * w2[(size_t)k * DDIM];
    p *= d_bucket_w[e * NTOK + r];
    float got = d_partial[((size_t)e * NTOK + r) * DDIM + cc];
    if (!isfinite(got) || fabsf(got - p) > 0.02f * fabsf(p) + 1e-3f)
        atomicExch(&d_bad, 1);
}

// =============================================================================
// SIMT fallbacks — R1-proven GEMMs, gated on d_bad.
// =============================================================================
#define TM 128
#define TN 64
#define TK 16

__global__ __launch_bounds__(256) void fb_up(
    const float* __restrict__ x, const float* __restrict__ W1,
    const float* __restrict__ W3)
{
    if (d_bad == 0) return;
    int e = blockIdx.z;
    int cnt = d_counts[e];
    int m0 = blockIdx.y * TM;
    if (m0 >= cnt) return;
    int n0 = blockIdx.x * TN;

    __shared__ float As[TK][TM];
    __shared__ float B1s[TK][TN];
    __shared__ float B3s[TK][TN];

    int tid = threadIdx.x;
    int tx = tid & 15, ty = tid >> 4;

    int lrow = tid >> 1;
    int lk = (tid & 1) * 8;
    int grow = m0 + lrow;
    int gi = grow < cnt ? grow : cnt - 1;
    int tok = d_bucket_tok[e * NTOK + gi];
    const float* xrow = x + (size_t)tok * DDIM + lk;

    int kb = tid >> 4, cb = (tid & 15) * 4;
    const float* w1p = W1 + (size_t)e * DDIM * HDIM + (size_t)kb * HDIM + n0 + cb;
    const float* w3p = W3 + (size_t)e * DDIM * HDIM + (size_t)kb * HDIM + n0 + cb;

    float c1[8][4], c2[8][4];
    #pragma unroll
    for (int i = 0; i < 8; i++)
        #pragma unroll
        for (int j = 0; j < 4; j++) { c1[i][j] = 0.f; c2[i][j] = 0.f; }

    for (int k0 = 0; k0 < DDIM; k0 += TK) {
        #pragma unroll
        for (int j = 0; j < 8; j++) As[lk + j][lrow] = xrow[k0 + j];
        float4 b1 = *(const float4*)(w1p + (size_t)k0 * HDIM);
        float4 b3 = *(const float4*)(w3p + (size_t)k0 * HDIM);
        *(float4*)&B1s[kb][cb] = b1;
        *(float4*)&B3s[kb][cb] = b3;
        __syncthreads();
        #pragma unroll
        for (int kk = 0; kk < TK; kk++) {
            float4 A0 = *(float4*)&As[kk][ty * 8];
            float4 A1 = *(float4*)&As[kk][ty * 8 + 4];
            float a[8] = {A0.x, A0.y, A0.z, A0.w, A1.x, A1.y, A1.z, A1.w};
            float4 bb1 = *(float4*)&B1s[kk][tx * 4];
            float4 bb3 = *(float4*)&B3s[kk][tx * 4];
            float bv1[4] = {bb1.x, bb1.y, bb1.z, bb1.w};
            float bv3[4] = {bb3.x, bb3.y, bb3.z, bb3.w};
            #pragma unroll
            for (int mi = 0; mi < 8; mi++)
                #pragma unroll
                for (int ni = 0; ni < 4; ni++) {
                    c1[mi][ni] += a[mi] * bv1[ni];
                    c2[mi][ni] += a[mi] * bv3[ni];
                }
        }
        __syncthreads();
    }

    float* hp = d_h32 + ((size_t)e * NTOK + m0) * HDIM + n0;
    #pragma unroll
    for (int mi = 0; mi < 8; mi++) {
        int r2 = ty * 8 + mi;
        #pragma unroll
        for (int ni = 0; ni < 4; ni++) {
            float a = c1[mi][ni];
            float hv = (a / (1.f + __expf(-a))) * c2[mi][ni];
            hp[(size_t)r2 * HDIM + tx * 4 + ni] = hv;
        }
    }
}

__global__ __launch_bounds__(256) void fb_down(const float* __restrict__ W2)
{
    if (d_bad == 0) return;
    int e = blockIdx.z;
    int cnt = d_counts[e];
    int m0 = blockIdx.y * TM;
    if (m0 >= cnt) return;
    int n0 = blockIdx.x * TN;

    __shared__ float As[TK][TM];
    __shared__ float Bs[TK][TN];

    int tid = threadIdx.x;
    int tx = tid & 15, ty = tid >> 4;

    int lrow = tid >> 1;
    int lk = (tid & 1) * 8;
    const float* hrow = d_h32 + ((size_t)e * NTOK + m0 + lrow) * HDIM + lk;

    int kb = tid >> 4, cb = (tid & 15) * 4;
    const float* w2p = W2 + (size_t)e * HDIM * DDIM + (size_t)kb * DDIM + n0 + cb;

    float c[8][4];
    #pragma unroll
    for (int i = 0; i < 8; i++)
        #pragma unroll
        for (int j = 0; j < 4; j++) c[i][j] = 0.f;

    for (int k0 = 0; k0 < HDIM; k0 += TK) {
        #pragma unroll
        for (int j = 0; j < 8; j++) As[lk + j][lrow] = hrow[k0 + j];
        float4 b = *(const float4*)(w2p + (size_t)k0 * DDIM);
        *(float4*)&Bs[kb][cb] = b;
        __syncthreads();
        #pragma unroll
        for (int kk = 0; kk < TK; kk++) {
            float4 A0 = *(float4*)&As[kk][ty * 8];
            float4 A1 = *(float4*)&As[kk][ty * 8 + 4];
            float a[8] = {A0.x, A0.y, A0.z, A0.w, A1.x, A1.y, A1.z, A1.w};
            float4 bb = *(float4*)&Bs[kk][tx * 4];
            float bv[4] = {bb.x, bb.y, bb.z, bb.w};
            #pragma unroll
            for (int mi = 0; mi < 8; mi++)
                #pragma unroll
                for (int ni = 0; ni < 4; ni++)
                    c[mi][ni] += a[mi] * bv[ni];
        }
        __syncthreads();
    }

    #pragma unroll
    for (int mi = 0; mi < 8; mi++) {
        int r2 = ty * 8 + mi;
        int gr = m0 + r2;
        float wrow = d_bucket_w[e * NTOK + gr];
        float* pp = d_partial + ((size_t)e * NTOK + gr) * DDIM + n0;
        #pragma unroll
        for (int ni = 0; ni < 4; ni++)
            pp[tx * 4 + ni] = c[mi][ni] * wrow;
    }
}

// ---------------- gather ----------------
__global__ __launch_bounds__(128) void gather_out(float* __restrict__ out) {
    int n = blockIdx.x;
    int tid = threadIdx.x;
    float acc[4] = {0.f, 0.f, 0.f, 0.f};
    #pragma unroll
    for (int e = 0; e < ENUM; e++) {
        int s = d_slot[n * ENUM + e];
        if (s >= 0) {
            const float* pp = d_partial + ((size_t)e * NTOK + s) * DDIM;
            #pragma unroll
            for (int q = 0; q < 4; q++) acc[q] += pp[tid + q * 128];
        }
    }
    #pragma unroll
    for (int q = 0; q < 4; q++) out[(size_t)n * DDIM + tid + q * 128] = acc[q];
}

// ---------------- launch ----------------
extern "C" void kernel_launch(void* const* d_in, const int* in_sizes, int n_in,
                              void* d_out, int out_size)
{
    const float* x  = (const float*)d_in[0];
    const float* Wr = (const float*)d_in[1];
    const float* br = (const float*)d_in[2];
    const float* Wg = (const float*)d_in[3];
    const float* bg = (const float*)d_in[4];
    const float* W1 = (const float*)d_in[5];
    const float* W3 = (const float*)d_in[6];
    const float* W2 = (const float*)d_in[7];
    float* out = (float*)d_out;

    routing_kernel<<<NTOK / 8, 256>>>(x, Wr, br, Wg, bg);   // launch 1
    build_buckets<<<ENUM, 256>>>();                          // launch 2
    zk<<<1, 32>>>();                                         // launch 3
    zk<<<1, 32>>>();                                         // launch 4
    zk<<<1, 32>>>();                                         // launch 5
    wmma_up<<<dim3(HDIM / 64, NTOK / 128, ENUM), 256>>>(x, W1, W3);   // launch 6 <- ncu
    wmma_down<<<dim3(DDIM / 128, NTOK / 128, ENUM), 256>>>(W2);       // launch 7
    verify_up<<<64, 256>>>(x, W1, W3);                       // launch 8
    verify_down<<<32, 256>>>(W2);                            // launch 9
    fb_up<<<dim3(HDIM / TN, NTOK / TM, ENUM), 256>>>(x, W1, W3);
    fb_down<<<dim3(DDIM / TN, NTOK / TM, ENUM), 256>>>(W2);
    gather_out<<<NTOK, 128>>>(out);
}

// round 8
// speedup vs baseline: 6.1671x; 1.3156x over previous
#include <cuda_runtime.h>
#include <cuda_fp16.h>
#include <mma.h>
#include <cstdint>

using namespace nvcuda;

#define NTOK 2048
#define DDIM 512
#define HDIM 2048
#define GNUM 4
#define EPG  4
#define ENUM 16
#define GTP_THR 0.9f
#define TP_THR  0.9f
#define SCALE_W 0.5f

// ---------------- scratch ----------------
__device__ float d_tw[NTOK * ENUM];
__device__ int   d_slot[NTOK * ENUM];
__device__ int   d_bucket_tok[ENUM * NTOK];
__device__ float d_bucket_w[ENUM * NTOK];
__device__ int   d_counts[ENUM];
__device__ int   d_bad;
__device__ float d_h32[(size_t)ENUM * NTOK * HDIM];     // 256 MB
__device__ float d_partial[(size_t)ENUM * NTOK * DDIM]; // 64 MB

// ---------------- helpers ----------------
__device__ __forceinline__ void cvt4(float4 v, __half* hi, __half* lo) {
    __half h0 = __float2half_rn(v.x), h1 = __float2half_rn(v.y),
           h2 = __float2half_rn(v.z), h3 = __float2half_rn(v.w);
    ((__half2*)hi)[0] = __halves2half2(h0, h1);
    ((__half2*)hi)[1] = __halves2half2(h2, h3);
    ((__half2*)lo)[0] = __halves2half2(__float2half_rn(v.x - __half2float(h0)),
                                       __float2half_rn(v.y - __half2float(h1)));
    ((__half2*)lo)[1] = __halves2half2(__float2half_rn(v.z - __half2float(h2)),
                                       __float2half_rn(v.w - __half2float(h3)));
}
__device__ __forceinline__ void cvthi4(float4 v, __half* hi) {
    ((__half2*)hi)[0] = __floats2half2_rn(v.x, v.y);
    ((__half2*)hi)[1] = __floats2half2_rn(v.z, v.w);
}

// ---------------- routing ----------------
__device__ __forceinline__ void top2norm(const float* logit, float thr, float* w) {
    float m = logit[0];
    #pragma unroll
    for (int i = 1; i < 4; i++) m = fmaxf(m, logit[i]);
    float p[4], s = 0.f;
    #pragma unroll
    for (int i = 0; i < 4; i++) { p[i] = expf(logit[i] - m); s += p[i]; }
    #pragma unroll
    for (int i = 0; i < 4; i++) p[i] /= s;
    int i0 = 0; float b0 = p[0];
    #pragma unroll
    for (int i = 1; i < 4; i++) if (p[i] > b0) { b0 = p[i]; i0 = i; }
    int i1 = -1; float b1 = -1.f;
    #pragma unroll
    for (int i = 0; i < 4; i++) if (i != i0 && p[i] > b1) { b1 = p[i]; i1 = i; }
    bool act1 = (b0 + b1) <= thr;
    float mp1 = act1 ? b1 : 0.f;
    float den = b0 + mp1 + 1e-9f;
    #pragma unroll
    for (int i = 0; i < 4; i++) w[i] = 0.f;
    w[i0] = b0 / den;
    w[i1] = mp1 / den;
}

__global__ __launch_bounds__(256) void routing_kernel(
    const float* __restrict__ x, const float* __restrict__ Wr,
    const float* __restrict__ br, const float* __restrict__ Wg,
    const float* __restrict__ bg)
{
    int wid = threadIdx.x >> 5, lane = threadIdx.x & 31;
    int n = blockIdx.x * 8 + wid;
    const float* xr = x + (size_t)n * DDIM;
    float xv[16];
    #pragma unroll
    for (int i = 0; i < 16; i++) xv[i] = xr[lane + 32 * i];

    float acc[20];
    #pragma unroll
    for (int g = 0; g < 4; g++) {
        float s = 0.f;
        #pragma unroll
        for (int i = 0; i < 16; i++) s += xv[i] * Wr[(lane + 32 * i) * 4 + g];
        acc[g] = s;
    }
    #pragma unroll
    for (int g = 0; g < 4; g++) {
        #pragma unroll
        for (int e = 0; e < 4; e++) {
            float s = 0.f;
            const float* wgp = Wg + (size_t)g * DDIM * EPG + e;
            #pragma unroll
            for (int i = 0; i < 16; i++) s += xv[i] * wgp[(lane + 32 * i) * 4];
            acc[4 + g * 4 + e] = s;
        }
    }
    #pragma unroll
    for (int o = 16; o; o >>= 1) {
        #pragma unroll
        for (int j = 0; j < 20; j++) acc[j] += __shfl_xor_sync(0xffffffffu, acc[j], o);
    }
    if (lane == 0) {
        float gl[4];
        #pragma unroll
        for (int g = 0; g < 4; g++) gl[g] = acc[g] + br[g];
        float wgrp[4];
        top2norm(gl, GTP_THR, wgrp);
        #pragma unroll
        for (int g = 0; g < 4; g++) {
            float el[4];
            #pragma unroll
            for (int e = 0; e < 4; e++) el[e] = acc[4 + g * 4 + e] + bg[g * 4 + e];
            float wexp[4];
            top2norm(el, TP_THR, wexp);
            #pragma unroll
            for (int e = 0; e < 4; e++) {
                d_tw[n * ENUM + g * 4 + e] = wgrp[g] * wexp[e] * SCALE_W;
                d_slot[n * ENUM + g * 4 + e] = -1;
            }
        }
    }
}

// ---------------- bucket build ----------------
__global__ __launch_bounds__(256) void build_buckets() {
    int e = blockIdx.x;
    int t = threadIdx.x;
    __shared__ int sc[256];
    int base = t * 8;
    float wv[8];
    int flags = 0, cnt = 0;
    #pragma unroll
    for (int j = 0; j < 8; j++) {
        float v = d_tw[(base + j) * ENUM + e];
        wv[j] = v;
        if (v > 0.f) { flags |= 1 << j; cnt++; }
    }
    sc[t] = cnt;
    __syncthreads();
    for (int off = 1; off < 256; off <<= 1) {
        int v = sc[t];
        int add = (t >= off) ? sc[t - off] : 0;
        __syncthreads();
        sc[t] = v + add;
        __syncthreads();
    }
    int pos = sc[t] - cnt;
    #pragma unroll
    for (int j = 0; j < 8; j++) {
        if ((flags >> j) & 1) {
            int n = base + j;
            d_bucket_tok[e * NTOK + pos] = n;
            d_bucket_w[e * NTOK + pos] = wv[j];
            d_slot[n * ENUM + e] = pos;
            pos++;
        }
    }
    if (t == 255) d_counts[e] = sc[255];
}

__global__ void zk() {
    if (threadIdx.x == 0 && blockIdx.x == 0) d_bad = 0;
}

// =============================================================================
// wmma_up: block 128(M) x 64(N), K-chunk 32, 8 warps (4m x 2n).
// A: fp16 hi/lo split (2-term). B (W1,W3): fp16 hi only.
// Register prefetch of next chunk overlaps global latency with MMA.
// SMEM halfs: Ah[128x40]@0  Al@5120  B1h[32x72]@10240  B3h@12544 (14848 halfs)
// =============================================================================
__global__ __launch_bounds__(256, 1) void wmma_up(
    const float* __restrict__ x, const float* __restrict__ W1,
    const float* __restrict__ W3)
{
    __shared__ __align__(16) __half SM[14848];
    int e = blockIdx.z;
    int cnt = d_counts[e];
    if (cnt == 0) return;
    int cntp = (cnt + 127) & ~127;
    int m0 = blockIdx.y * 128;
    if (m0 >= cntp) return;
    int n0 = blockIdx.x * 64;
    int tid = threadIdx.x, lane = tid & 31, wid = tid >> 5;
    int wm = wid & 3, wn = wid >> 2;

    __half* Ah = SM;
    __half* Al = SM + 5120;
    __half* B1h = SM + 10240;
    __half* B3h = SM + 12544;

    int ar = tid >> 1, ap = (tid & 1) * 16;
    int gi = m0 + ar; if (gi > cnt - 1) gi = cnt - 1;
    const float* xrow = x + (size_t)d_bucket_tok[e * NTOK + gi] * DDIM;
    int kB = tid >> 3, cB = (tid & 7) * 8;
    const float* w1p = W1 + (size_t)e * DDIM * HDIM + (size_t)kB * HDIM + n0 + cB;
    const float* w3p = W3 + (size_t)e * DDIM * HDIM + (size_t)kB * HDIM + n0 + cB;

    wmma::fragment<wmma::accumulator, 16, 16, 16, float> u[2][2], v[2][2];
    #pragma unroll
    for (int i = 0; i < 2; i++)
        #pragma unroll
        for (int j = 0; j < 2; j++) {
            wmma::fill_fragment(u[i][j], 0.0f);
            wmma::fill_fragment(v[i][j], 0.0f);
        }

    float4 ra[4], rb1[2], rb3[2];
    #pragma unroll
    for (int q = 0; q < 4; q++) ra[q] = *(const float4*)(xrow + ap + q * 4);
    rb1[0] = *(const float4*)(w1p);
    rb1[1] = *(const float4*)(w1p + 4);
    rb3[0] = *(const float4*)(w3p);
    rb3[1] = *(const float4*)(w3p + 4);

    for (int kc = 0; kc < DDIM / 32; kc++) {
        // store current regs (converted) to smem
        #pragma unroll
        for (int q = 0; q < 4; q++)
            cvt4(ra[q], Ah + ar * 40 + ap + q * 4, Al + ar * 40 + ap + q * 4);
        cvthi4(rb1[0], B1h + kB * 72 + cB);
        cvthi4(rb1[1], B1h + kB * 72 + cB + 4);
        cvthi4(rb3[0], B3h + kB * 72 + cB);
        cvthi4(rb3[1], B3h + kB * 72 + cB + 4);
        __syncthreads();
        // prefetch next chunk into regs (overlaps with mma below)
        if (kc + 1 < DDIM / 32) {
            int k1 = (kc + 1) * 32;
            #pragma unroll
            for (int q = 0; q < 4; q++) ra[q] = *(const float4*)(xrow + k1 + ap + q * 4);
            rb1[0] = *(const float4*)(w1p + (size_t)k1 * HDIM);
            rb1[1] = *(const float4*)(w1p + (size_t)k1 * HDIM + 4);
            rb3[0] = *(const float4*)(w3p + (size_t)k1 * HDIM);
            rb3[1] = *(const float4*)(w3p + (size_t)k1 * HDIM + 4);
        }
        #pragma unroll
        for (int ks = 0; ks < 2; ks++) {
            wmma::fragment<wmma::matrix_a, 16, 16, 16, __half, wmma::row_major> fah[2], fal[2];
            #pragma unroll
            for (int i = 0; i < 2; i++) {
                int ro = (wm * 32 + 16 * i) * 40 + ks * 16;
                wmma::load_matrix_sync(fah[i], Ah + ro, 40);
                wmma::load_matrix_sync(fal[i], Al + ro, 40);
            }
            wmma::fragment<wmma::matrix_b, 16, 16, 16, __half, wmma::row_major> f1h[2], f3h[2];
            #pragma unroll
            for (int j = 0; j < 2; j++) {
                int bo = ks * 16 * 72 + wn * 32 + 16 * j;
                wmma::load_matrix_sync(f1h[j], B1h + bo, 72);
                wmma::load_matrix_sync(f3h[j], B3h + bo, 72);
            }
            #pragma unroll
            for (int i = 0; i < 2; i++)
                #pragma unroll
                for (int j = 0; j < 2; j++) {
                    wmma::mma_sync(u[i][j], fah[i], f1h[j], u[i][j]);
                    wmma::mma_sync(u[i][j], fal[i], f1h[j], u[i][j]);
                    wmma::mma_sync(v[i][j], fah[i], f3h[j], v[i][j]);
                    wmma::mma_sync(v[i][j], fal[i], f3h[j], v[i][j]);
                }
        }
        __syncthreads();
    }

    float* epi = (float*)SM + wid * 576;
    int r = lane >> 1, c0 = (lane & 1) * 8;
    #pragma unroll
    for (int i = 0; i < 2; i++)
        #pragma unroll
        for (int j = 0; j < 2; j++) {
            #pragma unroll
            for (int t = 0; t < u[i][j].num_elements; t++) {
                float uu = u[i][j].x[t];
                u[i][j].x[t] = uu / (1.f + __expf(-uu)) * v[i][j].x[t];
            }
            wmma::store_matrix_sync(epi, u[i][j], 36, wmma::mem_row_major);
            __syncwarp();
            int grow = m0 + wm * 32 + 16 * i + r;
            int gcol = n0 + wn * 32 + 16 * j + c0;
            float* op = d_h32 + ((size_t)e * NTOK + grow) * HDIM + gcol;
            float4 o0 = { epi[r * 36 + c0],     epi[r * 36 + c0 + 1],
                          epi[r * 36 + c0 + 2], epi[r * 36 + c0 + 3] };
            float4 o1 = { epi[r * 36 + c0 + 4], epi[r * 36 + c0 + 5],
                          epi[r * 36 + c0 + 6], epi[r * 36 + c0 + 7] };
            *(float4*)op = o0;
            *(float4*)(op + 4) = o1;
            __syncwarp();
        }
}

// =============================================================================
// wmma_down: block 128(M) x 128(N), K-chunk 32, 8 warps (2m x 4n).
// A (h): fp16 hi/lo split. B (W2): fp16 hi only. Register prefetch.
// SMEM halfs: Ah[128x40]@0 Al@5120 Bh[32x136]@10240 (14592 halfs)
// =============================================================================
__global__ __launch_bounds__(256, 1) void wmma_down(const float* __restrict__ W2)
{
    __shared__ __align__(16) __half SM[14592];
    int e = blockIdx.z;
    int cnt = d_counts[e];
    if (cnt == 0) return;
    int cntp = (cnt + 127) & ~127;
    int m0 = blockIdx.y * 128;
    if (m0 >= cntp) return;
    int n0 = blockIdx.x * 128;
    int tid = threadIdx.x, lane = tid & 31, wid = tid >> 5;
    int wm = wid & 1, wn = wid >> 1;

    __half* Ah = SM;
    __half* Al = SM + 5120;
    __half* Bh = SM + 10240;

    int ar = tid >> 1, ap = (tid & 1) * 16;
    const float* arow = d_h32 + ((size_t)e * NTOK + m0 + ar) * HDIM;
    int kB = tid >> 3, cB = (tid & 7) * 16;
    const float* w2p = W2 + (size_t)e * HDIM * DDIM + (size_t)kB * DDIM + n0 + cB;

    wmma::fragment<wmma::accumulator, 16, 16, 16, float> c[4][2];
    #pragma unroll
    for (int f = 0; f < 4; f++)
        #pragma unroll
        for (int j = 0; j < 2; j++) wmma::fill_fragment(c[f][j], 0.0f);

    float4 ra[4], rb[4];
    #pragma unroll
    for (int q = 0; q < 4; q++) {
        ra[q] = *(const float4*)(arow + ap + q * 4);
        rb[q] = *(const float4*)(w2p + q * 4);
    }

    for (int kc = 0; kc < HDIM / 32; kc++) {
        #pragma unroll
        for (int q = 0; q < 4; q++) {
            cvt4(ra[q], Ah + ar * 40 + ap + q * 4, Al + ar * 40 + ap + q * 4);
            cvthi4(rb[q], Bh + kB * 136 + cB + q * 4);
        }
        __syncthreads();
        if (kc + 1 < HDIM / 32) {
            int k1 = (kc + 1) * 32;
            #pragma unroll
            for (int q = 0; q < 4; q++) {
                ra[q] = *(const float4*)(arow + k1 + ap + q * 4);
                rb[q] = *(const float4*)(w2p + (size_t)k1 * DDIM + q * 4);
            }
        }
        #pragma unroll
        for (int ks = 0; ks < 2; ks++) {
            wmma::fragment<wmma::matrix_a, 16, 16, 16, __half, wmma::row_major> fah[4], fal[4];
            #pragma unroll
            for (int f = 0; f < 4; f++) {
                int ro = (wm * 64 + 16 * f) * 40 + ks * 16;
                wmma::load_matrix_sync(fah[f], Ah + ro, 40);
                wmma::load_matrix_sync(fal[f], Al + ro, 40);
            }
            wmma::fragment<wmma::matrix_b, 16, 16, 16, __half, wmma::row_major> fbh[2];
            #pragma unroll
            for (int j = 0; j < 2; j++) {
                int bo = ks * 16 * 136 + wn * 32 + 16 * j;
                wmma::load_matrix_sync(fbh[j], Bh + bo, 136);
            }
            #pragma unroll
            for (int f = 0; f < 4; f++)
                #pragma unroll
                for (int j = 0; j < 2; j++) {
                    wmma::mma_sync(c[f][j], fah[f], fbh[j], c[f][j]);
                    wmma::mma_sync(c[f][j], fal[f], fbh[j], c[f][j]);
                }
        }
        __syncthreads();
    }

    float* epi = (float*)SM + wid * 576;
    int r = lane >> 1, c0 = (lane & 1) * 8;
    #pragma unroll
    for (int f = 0; f < 4; f++)
        #pragma unroll
        for (int j = 0; j < 2; j++) {
            wmma::store_matrix_sync(epi, c[f][j], 36, wmma::mem_row_major);
            __syncwarp();
            int grow = m0 + wm * 64 + 16 * f + r;
            float w = d_bucket_w[e * NTOK + grow];
            int gcol = n0 + wn * 32 + 16 * j + c0;
            float* op = d_partial + ((size_t)e * NTOK + grow) * DDIM + gcol;
            float4 o0 = { epi[r * 36 + c0] * w,     epi[r * 36 + c0 + 1] * w,
                          epi[r * 36 + c0 + 2] * w, epi[r * 36 + c0 + 3] * w };
            float4 o1 = { epi[r * 36 + c0 + 4] * w, epi[r * 36 + c0 + 5] * w,
                          epi[r * 36 + c0 + 6] * w, epi[r * 36 + c0 + 7] * w };
            *(float4*)op = o0;
            *(float4*)(op + 4) = o1;
            __syncwarp();
        }
}

// =============================================================================
// verify kernels
// =============================================================================
__global__ __launch_bounds__(256) void verify_up(
    const float* __restrict__ x, const float* __restrict__ W1,
    const float* __restrict__ W3)
{
    int b = blockIdx.x;
    int e = b & 15;
    int cnt = d_counts[e];
    if (cnt == 0) return;
    int sr = b >> 4;
    int r = (sr * 577 + 31) % cnt;
    int tok = d_bucket_tok[e * NTOK + r];
    int cc = sr * 512 + threadIdx.x;
    const float* xr = x + (size_t)tok * DDIM;
    const float* w1 = W1 + (size_t)e * DDIM * HDIM + cc;
    const float* w3 = W3 + (size_t)e * DDIM * HDIM + cc;
    float u = 0.f, v = 0.f;
    for (int k = 0; k < DDIM; k++) {
        float xv = xr[k];
        u += xv * w1[(size_t)k * HDIM];
        v += xv * w3[(size_t)k * HDIM];
    }
    float href = u / (1.f + __expf(-u)) * v;
    float got = d_h32[((size_t)e * NTOK + r) * HDIM + cc];
    if (!isfinite(got) || fabsf(got - href) > 0.02f * fabsf(href) + 1e-3f)
        atomicExch(&d_bad, 1);
}

__global__ __launch_bounds__(256) void verify_down(const float* __restrict__ W2)
{
    int b = blockIdx.x;
    int e = b & 15;
    int cnt = d_counts[e];
    if (cnt == 0) return;
    int sr = b >> 4;
    int r = (sr * 911 + 17) % cnt;
    int cc = sr * 256 + threadIdx.x;
    const float* hrow = d_h32 + ((size_t)e * NTOK + r) * HDIM;
    const float* w2 = W2 + (size_t)e * HDIM * DDIM + cc;
    float p = 0.f;
    for (int k = 0; k < HDIM; k++)
        p += hrow[k] * w2[(size_t)k * DDIM];
    p *= d_bucket_w[e * NTOK + r];
    float got = d_partial[((size_t)e * NTOK + r) * DDIM + cc];
    if (!isfinite(got) || fabsf(got - p) > 0.02f * fabsf(p) + 1e-3f)
        atomicExch(&d_bad, 1);
}

// =============================================================================
// SIMT fallbacks (gated on d_bad)
// =============================================================================
#define TM 128
#define TN 64
#define TK 16

__global__ __launch_bounds__(256) void fb_up(
    const float* __restrict__ x, const float* __restrict__ W1,
    const float* __restrict__ W3)
{
    if (d_bad == 0) return;
    int e = blockIdx.z;
    int cnt = d_counts[e];
    int m0 = blockIdx.y * TM;
    if (m0 >= cnt) return;
    int n0 = blockIdx.x * TN;

    __shared__ float As[TK][TM];
    __shared__ float B1s[TK][TN];
    __shared__ float B3s[TK][TN];

    int tid = threadIdx.x;
    int tx = tid & 15, ty = tid >> 4;

    int lrow = tid >> 1;
    int lk = (tid & 1) * 8;
    int grow = m0 + lrow;
    int gi = grow < cnt ? grow : cnt - 1;
    int tok = d_bucket_tok[e * NTOK + gi];
    const float* xrow = x + (size_t)tok * DDIM + lk;

    int kb = tid >> 4, cb = (tid & 15) * 4;
    const float* w1p = W1 + (size_t)e * DDIM * HDIM + (size_t)kb * HDIM + n0 + cb;
    const float* w3p = W3 + (size_t)e * DDIM * HDIM + (size_t)kb * HDIM + n0 + cb;

    float c1[8][4], c2[8][4];
    #pragma unroll
    for (int i = 0; i < 8; i++)
        #pragma unroll
        for (int j = 0; j < 4; j++) { c1[i][j] = 0.f; c2[i][j] = 0.f; }

    for (int k0 = 0; k0 < DDIM; k0 += TK) {
        #pragma unroll
        for (int j = 0; j < 8; j++) As[lk + j][lrow] = xrow[k0 + j];
        float4 b1 = *(const float4*)(w1p + (size_t)k0 * HDIM);
        float4 b3 = *(const float4*)(w3p + (size_t)k0 * HDIM);
        *(float4*)&B1s[kb][cb] = b1;
        *(float4*)&B3s[kb][cb] = b3;
        __syncthreads();
        #pragma unroll
        for (int kk = 0; kk < TK; kk++) {
            float4 A0 = *(float4*)&As[kk][ty * 8];
            float4 A1 = *(float4*)&As[kk][ty * 8 + 4];
            float a[8] = {A0.x, A0.y, A0.z, A0.w, A1.x, A1.y, A1.z, A1.w};
            float4 bb1 = *(float4*)&B1s[kk][tx * 4];
            float4 bb3 = *(float4*)&B3s[kk][tx * 4];
            float bv1[4] = {bb1.x, bb1.y, bb1.z, bb1.w};
            float bv3[4] = {bb3.x, bb3.y, bb3.z, bb3.w};
            #pragma unroll
            for (int mi = 0; mi < 8; mi++)
                #pragma unroll
                for (int ni = 0; ni < 4; ni++) {
                    c1[mi][ni] += a[mi] * bv1[ni];
                    c2[mi][ni] += a[mi] * bv3[ni];
                }
        }
        __syncthreads();
    }

    float* hp = d_h32 + ((size_t)e * NTOK + m0) * HDIM + n0;
    #pragma unroll
    for (int mi = 0; mi < 8; mi++) {
        int r2 = ty * 8 + mi;
        #pragma unroll
        for (int ni = 0; ni < 4; ni++) {
            float a = c1[mi][ni];
            float hv = (a / (1.f + __expf(-a))) * c2[mi][ni];
            hp[(size_t)r2 * HDIM + tx * 4 + ni] = hv;
        }
    }
}

__global__ __launch_bounds__(256) void fb_down(const float* __restrict__ W2)
{
    if (d_bad == 0) return;
    int e = blockIdx.z;
    int cnt = d_counts[e];
    int m0 = blockIdx.y * TM;
    if (m0 >= cnt) return;
    int n0 = blockIdx.x * TN;

    __shared__ float As[TK][TM];
    __shared__ float Bs[TK][TN];

    int tid = threadIdx.x;
    int tx = tid & 15, ty = tid >> 4;

    int lrow = tid >> 1;
    int lk = (tid & 1) * 8;
    const float* hrow = d_h32 + ((size_t)e * NTOK + m0 + lrow) * HDIM + lk;

    int kb = tid >> 4, cb = (tid & 15) * 4;
    const float* w2p = W2 + (size_t)e * HDIM * DDIM + (size_t)kb * DDIM + n0 + cb;

    float c[8][4];
    #pragma unroll
    for (int i = 0; i < 8; i++)
        #pragma unroll
        for (int j = 0; j < 4; j++) c[i][j] = 0.f;

    for (int k0 = 0; k0 < HDIM; k0 += TK) {
        #pragma unroll
        for (int j = 0; j < 8; j++) As[lk + j][lrow] = hrow[k0 + j];
        float4 b = *(const float4*)(w2p + (size_t)k0 * DDIM);
        *(float4*)&Bs[kb][cb] = b;
        __syncthreads();
        #pragma unroll
        for (int kk = 0; kk < TK; kk++) {
            float4 A0 = *(float4*)&As[kk][ty * 8];
            float4 A1 = *(float4*)&As[kk][ty * 8 + 4];
            float a[8] = {A0.x, A0.y, A0.z, A0.w, A1.x, A1.y, A1.z, A1.w};
            float4 bb = *(float4*)&Bs[kk][tx * 4];
            float bv[4] = {bb.x, bb.y, bb.z, bb.w};
            #pragma unroll
            for (int mi = 0; mi < 8; mi++)
                #pragma unroll
                for (int ni = 0; ni < 4; ni++)
                    c[mi][ni] += a[mi] * bv[ni];
        }
        __syncthreads();
    }

    #pragma unroll
    for (int mi = 0; mi < 8; mi++) {
        int r2 = ty * 8 + mi;
        int gr = m0 + r2;
        float wrow = d_bucket_w[e * NTOK + gr];
        float* pp = d_partial + ((size_t)e * NTOK + gr) * DDIM + n0;
        #pragma unroll
        for (int ni = 0; ni < 4; ni++)
            pp[tx * 4 + ni] = c[mi][ni] * wrow;
    }
}

// ---------------- gather ----------------
__global__ __launch_bounds__(128) void gather_out(float* __restrict__ out) {
    int n = blockIdx.x;
    int tid = threadIdx.x;
    float acc[4] = {0.f, 0.f, 0.f, 0.f};
    #pragma unroll
    for (int e = 0; e < ENUM; e++) {
        int s = d_slot[n * ENUM + e];
        if (s >= 0) {
            const float* pp = d_partial + ((size_t)e * NTOK + s) * DDIM;
            #pragma unroll
            for (int q = 0; q < 4; q++) acc[q] += pp[tid + q * 128];
        }
    }
    #pragma unroll
    for (int q = 0; q < 4; q++) out[(size_t)n * DDIM + tid + q * 128] = acc[q];
}

// ---------------- launch ----------------
extern "C" void kernel_launch(void* const* d_in, const int* in_sizes, int n_in,
                              void* d_out, int out_size)
{
    const float* x  = (const float*)d_in[0];
    const float* Wr = (const float*)d_in[1];
    const float* br = (const float*)d_in[2];
    const float* Wg = (const float*)d_in[3];
    const float* bg = (const float*)d_in[4];
    const float* W1 = (const float*)d_in[5];
    const float* W3 = (const float*)d_in[6];
    const float* W2 = (const float*)d_in[7];
    float* out = (float*)d_out;

    routing_kernel<<<NTOK / 8, 256>>>(x, Wr, br, Wg, bg);              // 1
    build_buckets<<<ENUM, 256>>>();                                     // 2
    zk<<<1, 32>>>();                                                    // 3
    wmma_up<<<dim3(HDIM / 64, NTOK / 128, ENUM), 256>>>(x, W1, W3);    // 4 <- ncu
    wmma_down<<<dim3(DDIM / 128, NTOK / 128, ENUM), 256>>>(W2);        // 5
    verify_up<<<64, 256>>>(x, W1, W3);                                  // 6
    verify_down<<<32, 256>>>(W2);                                       // 7
    fb_up<<<dim3(HDIM / TN, NTOK / TM, ENUM), 256>>>(x, W1, W3);       // 8
    fb_down<<<dim3(DDIM / TN, NTOK / TM, ENUM), 256>>>(W2);            // 9
    gather_out<<<NTOK, 128>>>(out);                                     // 10
}

// round 9
// speedup vs baseline: 10.4035x; 1.6869x over previous
#include <cuda_runtime.h>
#include <cuda_fp16.h>
#include <mma.h>
#include <cstdint>

using namespace nvcuda;

#define NTOK 2048
#define DDIM 512
#define HDIM 2048
#define GNUM 4
#define EPG  4
#define ENUM 16
#define GTP_THR 0.9f
#define TP_THR  0.9f
#define SCALE_W 0.5f

// ---------------- scratch ----------------
__device__ float d_tw[NTOK * ENUM];
__device__ int   d_slot[NTOK * ENUM];
__device__ int   d_bucket_tok[ENUM * NTOK];
__device__ float d_bucket_w[ENUM * NTOK];
__device__ int   d_counts[ENUM];
__device__ float d_h32[(size_t)ENUM * NTOK * HDIM];     // 256 MB
__device__ float d_partial[(size_t)ENUM * NTOK * DDIM]; // 64 MB

// ---------------- helpers ----------------
__device__ __forceinline__ void cvthi4(float4 v, __half* hi) {
    ((__half2*)hi)[0] = __floats2half2_rn(v.x, v.y);
    ((__half2*)hi)[1] = __floats2half2_rn(v.z, v.w);
}

// ---------------- routing ----------------
__device__ __forceinline__ void top2norm(const float* logit, float thr, float* w) {
    float m = logit[0];
    #pragma unroll
    for (int i = 1; i < 4; i++) m = fmaxf(m, logit[i]);
    float p[4], s = 0.f;
    #pragma unroll
    for (int i = 0; i < 4; i++) { p[i] = expf(logit[i] - m); s += p[i]; }
    #pragma unroll
    for (int i = 0; i < 4; i++) p[i] /= s;
    int i0 = 0; float b0 = p[0];
    #pragma unroll
    for (int i = 1; i < 4; i++) if (p[i] > b0) { b0 = p[i]; i0 = i; }
    int i1 = -1; float b1 = -1.f;
    #pragma unroll
    for (int i = 0; i < 4; i++) if (i != i0 && p[i] > b1) { b1 = p[i]; i1 = i; }
    bool act1 = (b0 + b1) <= thr;
    float mp1 = act1 ? b1 : 0.f;
    float den = b0 + mp1 + 1e-9f;
    #pragma unroll
    for (int i = 0; i < 4; i++) w[i] = 0.f;
    w[i0] = b0 / den;
    w[i1] = mp1 / den;
}

__global__ __launch_bounds__(256) void routing_kernel(
    const float* __restrict__ x, const float* __restrict__ Wr,
    const float* __restrict__ br, const float* __restrict__ Wg,
    const float* __restrict__ bg)
{
    int wid = threadIdx.x >> 5, lane = threadIdx.x & 31;
    int n = blockIdx.x * 8 + wid;
    const float* xr = x + (size_t)n * DDIM;
    float xv[16];
    #pragma unroll
    for (int i = 0; i < 16; i++) xv[i] = xr[lane + 32 * i];

    float acc[20];
    #pragma unroll
    for (int g = 0; g < 4; g++) {
        float s = 0.f;
        #pragma unroll
        for (int i = 0; i < 16; i++) s += xv[i] * Wr[(lane + 32 * i) * 4 + g];
        acc[g] = s;
    }
    #pragma unroll
    for (int g = 0; g < 4; g++) {
        #pragma unroll
        for (int e = 0; e < 4; e++) {
            float s = 0.f;
            const float* wgp = Wg + (size_t)g * DDIM * EPG + e;
            #pragma unroll
            for (int i = 0; i < 16; i++) s += xv[i] * wgp[(lane + 32 * i) * 4];
            acc[4 + g * 4 + e] = s;
        }
    }
    #pragma unroll
    for (int o = 16; o; o >>= 1) {
        #pragma unroll
        for (int j = 0; j < 20; j++) acc[j] += __shfl_xor_sync(0xffffffffu, acc[j], o);
    }
    if (lane == 0) {
        float gl[4];
        #pragma unroll
        for (int g = 0; g < 4; g++) gl[g] = acc[g] + br[g];
        float wgrp[4];
        top2norm(gl, GTP_THR, wgrp);
        #pragma unroll
        for (int g = 0; g < 4; g++) {
            float el[4];
            #pragma unroll
            for (int e = 0; e < 4; e++) el[e] = acc[4 + g * 4 + e] + bg[g * 4 + e];
            float wexp[4];
            top2norm(el, TP_THR, wexp);
            #pragma unroll
            for (int e = 0; e < 4; e++) {
                d_tw[n * ENUM + g * 4 + e] = wgrp[g] * wexp[e] * SCALE_W;
                d_slot[n * ENUM + g * 4 + e] = -1;
            }
        }
    }
}

// ---------------- bucket build ----------------
__global__ __launch_bounds__(256) void build_buckets() {
    int e = blockIdx.x;
    int t = threadIdx.x;
    __shared__ int sc[256];
    int base = t * 8;
    float wv[8];
    int flags = 0, cnt = 0;
    #pragma unroll
    for (int j = 0; j < 8; j++) {
        float v = d_tw[(base + j) * ENUM + e];
        wv[j] = v;
        if (v > 0.f) { flags |= 1 << j; cnt++; }
    }
    sc[t] = cnt;
    __syncthreads();
    for (int off = 1; off < 256; off <<= 1) {
        int v = sc[t];
        int add = (t >= off) ? sc[t - off] : 0;
        __syncthreads();
        sc[t] = v + add;
        __syncthreads();
    }
    int pos = sc[t] - cnt;
    #pragma unroll
    for (int j = 0; j < 8; j++) {
        if ((flags >> j) & 1) {
            int n = base + j;
            d_bucket_tok[e * NTOK + pos] = n;
            d_bucket_w[e * NTOK + pos] = wv[j];
            d_slot[n * ENUM + e] = pos;
            pos++;
        }
    }
    if (t == 255) d_counts[e] = sc[255];
}

// =============================================================================
// wmma_up: block 128(M) x 64(N), K-chunk 32, 8 warps (4m x 2n), warp 32x32.
// Pure fp16-hi operands, fp32 accumulation. Double-buffered smem, 1 sync/chunk.
// Stage (halfs): Ah[128x40]@0  B1h[32x72]@5120  B3h[32x72]@7424  (9728 halfs)
// =============================================================================
__global__ __launch_bounds__(256, 1) void wmma_up(
    const float* __restrict__ x, const float* __restrict__ W1,
    const float* __restrict__ W3)
{
    __shared__ __align__(16) __half SM[2][9728];   // 38912 B
    int e = blockIdx.z;
    int cnt = d_counts[e];
    if (cnt == 0) return;
    int cntp = (cnt + 127) & ~127;
    int m0 = blockIdx.y * 128;
    if (m0 >= cntp) return;
    int n0 = blockIdx.x * 64;
    int tid = threadIdx.x, lane = tid & 31, wid = tid >> 5;
    int wm = wid & 3, wn = wid >> 2;

    int ar = tid >> 1, ap = (tid & 1) * 16;
    int gi = m0 + ar; if (gi > cnt - 1) gi = cnt - 1;
    const float* xrow = x + (size_t)d_bucket_tok[e * NTOK + gi] * DDIM;
    int kB = tid >> 3, cB = (tid & 7) * 8;
    const float* w1p = W1 + (size_t)e * DDIM * HDIM + (size_t)kB * HDIM + n0 + cB;
    const float* w3p = W3 + (size_t)e * DDIM * HDIM + (size_t)kB * HDIM + n0 + cB;

    wmma::fragment<wmma::accumulator, 16, 16, 16, float> u[2][2], v[2][2];
    #pragma unroll
    for (int i = 0; i < 2; i++)
        #pragma unroll
        for (int j = 0; j < 2; j++) {
            wmma::fill_fragment(u[i][j], 0.0f);
            wmma::fill_fragment(v[i][j], 0.0f);
        }

    float4 ra[4], rb1[2], rb3[2];
    #pragma unroll
    for (int q = 0; q < 4; q++) ra[q] = *(const float4*)(xrow + ap + q * 4);
    rb1[0] = *(const float4*)(w1p);
    rb1[1] = *(const float4*)(w1p + 4);
    rb3[0] = *(const float4*)(w3p);
    rb3[1] = *(const float4*)(w3p + 4);

    for (int kc = 0; kc < DDIM / 32; kc++) {
        int b = kc & 1;
        __half* Ah = SM[b];
        __half* B1h = SM[b] + 5120;
        __half* B3h = SM[b] + 7424;
        #pragma unroll
        for (int q = 0; q < 4; q++)
            cvthi4(ra[q], Ah + ar * 40 + ap + q * 4);
        cvthi4(rb1[0], B1h + kB * 72 + cB);
        cvthi4(rb1[1], B1h + kB * 72 + cB + 4);
        cvthi4(rb3[0], B3h + kB * 72 + cB);
        cvthi4(rb3[1], B3h + kB * 72 + cB + 4);
        if (kc + 1 < DDIM / 32) {
            int k1 = (kc + 1) * 32;
            #pragma unroll
            for (int q = 0; q < 4; q++) ra[q] = *(const float4*)(xrow + k1 + ap + q * 4);
            rb1[0] = *(const float4*)(w1p + (size_t)k1 * HDIM);
            rb1[1] = *(const float4*)(w1p + (size_t)k1 * HDIM + 4);
            rb3[0] = *(const float4*)(w3p + (size_t)k1 * HDIM);
            rb3[1] = *(const float4*)(w3p + (size_t)k1 * HDIM + 4);
        }
        __syncthreads();
        #pragma unroll
        for (int ks = 0; ks < 2; ks++) {
            wmma::fragment<wmma::matrix_a, 16, 16, 16, __half, wmma::row_major> fah[2];
            #pragma unroll
            for (int i = 0; i < 2; i++)
                wmma::load_matrix_sync(fah[i], Ah + (wm * 32 + 16 * i) * 40 + ks * 16, 40);
            wmma::fragment<wmma::matrix_b, 16, 16, 16, __half, wmma::row_major> f1h[2], f3h[2];
            #pragma unroll
            for (int j = 0; j < 2; j++) {
                int bo = ks * 16 * 72 + wn * 32 + 16 * j;
                wmma::load_matrix_sync(f1h[j], B1h + bo, 72);
                wmma::load_matrix_sync(f3h[j], B3h + bo, 72);
            }
            #pragma unroll
            for (int i = 0; i < 2; i++)
                #pragma unroll
                for (int j = 0; j < 2; j++) {
                    wmma::mma_sync(u[i][j], fah[i], f1h[j], u[i][j]);
                    wmma::mma_sync(v[i][j], fah[i], f3h[j], v[i][j]);
                }
        }
        // no trailing sync: next iter writes the other buffer; the WAR on this
        // buffer (rewritten at kc+2) is separated by the sync at kc+1.
    }
    __syncthreads();   // tiles dead; alias SM as fp32 epilogue staging

    float* epi = (float*)SM + wid * 576;
    int r = lane >> 1, c0 = (lane & 1) * 8;
    #pragma unroll
    for (int i = 0; i < 2; i++)
        #pragma unroll
        for (int j = 0; j < 2; j++) {
            #pragma unroll
            for (int t = 0; t < u[i][j].num_elements; t++) {
                float uu = u[i][j].x[t];
                u[i][j].x[t] = uu / (1.f + __expf(-uu)) * v[i][j].x[t];
            }
            wmma::store_matrix_sync(epi, u[i][j], 36, wmma::mem_row_major);
            __syncwarp();
            int grow = m0 + wm * 32 + 16 * i + r;
            int gcol = n0 + wn * 32 + 16 * j + c0;
            float* op = d_h32 + ((size_t)e * NTOK + grow) * HDIM + gcol;
            float4 o0 = { epi[r * 36 + c0],     epi[r * 36 + c0 + 1],
                          epi[r * 36 + c0 + 2], epi[r * 36 + c0 + 3] };
            float4 o1 = { epi[r * 36 + c0 + 4], epi[r * 36 + c0 + 5],
                          epi[r * 36 + c0 + 6], epi[r * 36 + c0 + 7] };
            *(float4*)op = o0;
            *(float4*)(op + 4) = o1;
            __syncwarp();
        }
}

// =============================================================================
// wmma_down: block 128(M) x 128(N), K-chunk 32, 8 warps (4m x 2n), warp 32x64.
// Pure fp16-hi operands, fp32 accumulation. Double-buffered smem, 1 sync/chunk.
// Stage (halfs): Ah[128x40]@0  Bh[32x136]@5120  (9472 halfs)
// =============================================================================
__global__ __launch_bounds__(256, 1) void wmma_down(const float* __restrict__ W2)
{
    __shared__ __align__(16) __half SM[2][9472];   // 37888 B
    int e = blockIdx.z;
    int cnt = d_counts[e];
    if (cnt == 0) return;
    int cntp = (cnt + 127) & ~127;
    int m0 = blockIdx.y * 128;
    if (m0 >= cntp) return;
    int n0 = blockIdx.x * 128;
    int tid = threadIdx.x, lane = tid & 31, wid = tid >> 5;
    int wm = wid & 3, wn = wid >> 2;

    int ar = tid >> 1, ap = (tid & 1) * 16;
    const float* arow = d_h32 + ((size_t)e * NTOK + m0 + ar) * HDIM;
    int kB = tid >> 3, cB = (tid & 7) * 16;
    const float* w2p = W2 + (size_t)e * HDIM * DDIM + (size_t)kB * DDIM + n0 + cB;

    wmma::fragment<wmma::accumulator, 16, 16, 16, float> c[2][4];
    #pragma unroll
    for (int i = 0; i < 2; i++)
        #pragma unroll
        for (int j = 0; j < 4; j++) wmma::fill_fragment(c[i][j], 0.0f);

    float4 ra[4], rb[4];
    #pragma unroll
    for (int q = 0; q < 4; q++) {
        ra[q] = *(const float4*)(arow + ap + q * 4);
        rb[q] = *(const float4*)(w2p + q * 4);
    }

    for (int kc = 0; kc < HDIM / 32; kc++) {
        int b = kc & 1;
        __half* Ah = SM[b];
        __half* Bh = SM[b] + 5120;
        #pragma unroll
        for (int q = 0; q < 4; q++) {
            cvthi4(ra[q], Ah + ar * 40 + ap + q * 4);
            cvthi4(rb[q], Bh + kB * 136 + cB + q * 4);
        }
        if (kc + 1 < HDIM / 32) {
            int k1 = (kc + 1) * 32;
            #pragma unroll
            for (int q = 0; q < 4; q++) {
                ra[q] = *(const float4*)(arow + k1 + ap + q * 4);
                rb[q] = *(const float4*)(w2p + (size_t)k1 * DDIM + q * 4);
            }
        }
        __syncthreads();
        #pragma unroll
        for (int ks = 0; ks < 2; ks++) {
            wmma::fragment<wmma::matrix_a, 16, 16, 16, __half, wmma::row_major> fah[2];
            #pragma unroll
            for (int i = 0; i < 2; i++)
                wmma::load_matrix_sync(fah[i], Ah + (wm * 32 + 16 * i) * 40 + ks * 16, 40);
            wmma::fragment<wmma::matrix_b, 16, 16, 16, __half, wmma::row_major> fbh[4];
            #pragma unroll
            for (int j = 0; j < 4; j++)
                wmma::load_matrix_sync(fbh[j], Bh + ks * 16 * 136 + wn * 64 + 16 * j, 136);
            #pragma unroll
            for (int i = 0; i < 2; i++)
                #pragma unroll
                for (int j = 0; j < 4; j++)
                    wmma::mma_sync(c[i][j], fah[i], fbh[j], c[i][j]);
        }
    }
    __syncthreads();

    float* epi = (float*)SM + wid * 576;
    int r = lane >> 1, c0 = (lane & 1) * 8;
    #pragma unroll
    for (int i = 0; i < 2; i++)
        #pragma unroll
        for (int j = 0; j < 4; j++) {
            wmma::store_matrix_sync(epi, c[i][j], 36, wmma::mem_row_major);
            __syncwarp();
            int grow = m0 + wm * 32 + 16 * i + r;
            float w = d_bucket_w[e * NTOK + grow];
            int gcol = n0 + wn * 64 + 16 * j + c0;
            float* op = d_partial + ((size_t)e * NTOK + grow) * DDIM + gcol;
            float4 o0 = { epi[r * 36 + c0] * w,     epi[r * 36 + c0 + 1] * w,
                          epi[r * 36 + c0 + 2] * w, epi[r * 36 + c0 + 3] * w };
            float4 o1 = { epi[r * 36 + c0 + 4] * w, epi[r * 36 + c0 + 5] * w,
                          epi[r * 36 + c0 + 6] * w, epi[r * 36 + c0 + 7] * w };
            *(float4*)op = o0;
            *(float4*)(op + 4) = o1;
            __syncwarp();
        }
}

// ---------------- gather ----------------
__global__ __launch_bounds__(128) void gather_out(float* __restrict__ out) {
    int n = blockIdx.x;
    int tid = threadIdx.x;
    float acc[4] = {0.f, 0.f, 0.f, 0.f};
    #pragma unroll
    for (int e = 0; e < ENUM; e++) {
        int s = d_slot[n * ENUM + e];
        if (s >= 0) {
            const float* pp = d_partial + ((size_t)e * NTOK + s) * DDIM;
            #pragma unroll
            for (int q = 0; q < 4; q++) acc[q] += pp[tid + q * 128];
        }
    }
    #pragma unroll
    for (int q = 0; q < 4; q++) out[(size_t)n * DDIM + tid + q * 128] = acc[q];
}

// ---------------- launch ----------------
extern "C" void kernel_launch(void* const* d_in, const int* in_sizes, int n_in,
                              void* d_out, int out_size)
{
    const float* x  = (const float*)d_in[0];
    const float* Wr = (const float*)d_in[1];
    const float* br = (const float*)d_in[2];
    const float* Wg = (const float*)d_in[3];
    const float* bg = (const float*)d_in[4];
    const float* W1 = (const float*)d_in[5];
    const float* W3 = (const float*)d_in[6];
    const float* W2 = (const float*)d_in[7];
    float* out = (float*)d_out;

    routing_kernel<<<NTOK / 8, 256>>>(x, Wr, br, Wg, bg);              // 1
    build_buckets<<<ENUM, 256>>>();                                     // 2
    wmma_up<<<dim3(HDIM / 64, NTOK / 128, ENUM), 256>>>(x, W1, W3);    // 3
    wmma_down<<<dim3(DDIM / 128, NTOK / 128, ENUM), 256>>>(W2);        // 4 <- ncu
    gather_out<<<NTOK, 128>>>(out);                                     // 5
}